// round 4
// baseline (speedup 1.0000x reference)
#include <cuda_runtime.h>
#include <cuda_bf16.h>
#include <math.h>
#include <cstdint>

// ---------------- problem constants ----------------
#define B_GRAPHS 2048
#define F_NODES  64
#define D_IN     32
#define HDIM     128
#define HEADS    4
#define NC       16
#define EPG      128
#define N_NODES  (B_GRAPHS * F_NODES)        // 131072
#define E_EDGES  (B_GRAPHS * EPG)            // 262144

// ---------------- device-global weights (prepped once per call) ----------------
__device__ __nv_bfloat16 g_w1t_h[512 * 32];   // (Wa@W1)^T rows n, cols k   [512][32]
__device__ __nv_bfloat16 g_w1t_l[512 * 32];
__device__ float         g_c1[512];           // b_align @ W1
__device__ __nv_bfloat16 g_w2t_h[128 * 512];  // W2^T rows n, cols k        [128][512]
__device__ __nv_bfloat16 g_w2t_l[128 * 512];

// ---------------- PTX helpers (sm_80+ compatible) ----------------
__device__ __forceinline__ uint32_t smem_to_u32(const void* p) {
    uint32_t a;
    asm("{ .reg .u64 tmp; cvta.to.shared.u64 tmp, %1; cvt.u32.u64 %0, tmp; }" : "=r"(a) : "l"(p));
    return a;
}
__device__ __forceinline__ void cp16(uint32_t saddr, const void* g) {
    asm volatile("cp.async.cg.shared.global [%0], [%1], 16;"
                 :: "r"(saddr), "l"(g) : "memory");
}
#define CP_COMMIT() asm volatile("cp.async.commit_group;" ::: "memory")
#define CP_WAIT0()  asm volatile("cp.async.wait_group 0;" ::: "memory")
#define CP_WAIT1()  asm volatile("cp.async.wait_group 1;" ::: "memory")

#define LDSM_X4(r0, r1, r2, r3, addr) \
    asm volatile("ldmatrix.sync.aligned.m8n8.x4.shared.b16 {%0,%1,%2,%3}, [%4];" \
                 : "=r"(r0), "=r"(r1), "=r"(r2), "=r"(r3) : "r"(addr))

#define MMA16816(d, a, b0, b1) \
    asm volatile("mma.sync.aligned.m16n8k16.row.col.f32.bf16.bf16.f32 " \
                 "{%0,%1,%2,%3}, {%4,%5,%6,%7}, {%8,%9}, {%0,%1,%2,%3};" \
                 : "+f"((d)[0]), "+f"((d)[1]), "+f"((d)[2]), "+f"((d)[3]) \
                 : "r"((a)[0]), "r"((a)[1]), "r"((a)[2]), "r"((a)[3]), "r"(b0), "r"(b1))

__device__ __forceinline__ void split2(float x, float y, uint32_t& hi, uint32_t& lo) {
    __nv_bfloat16 hx = __float2bfloat16(x), hy = __float2bfloat16(y);
    __nv_bfloat162 H(hx, hy);
    __nv_bfloat162 L(__float2bfloat16(x - __bfloat162float(hx)),
                     __float2bfloat16(y - __bfloat162float(hy)));
    hi = *(uint32_t*)&H;
    lo = *(uint32_t*)&L;
}

__device__ __forceinline__ void atomicMaxFloatS(float* addr, float val) {
    int* ai = (int*)addr;
    int old = *ai;
    while (__int_as_float(old) < val) {
        int assumed = old;
        old = atomicCAS(ai, assumed, __float_as_int(val));
        if (old == assumed) break;
    }
}

// ---------------- prep: fused/transposed weights, single launch ----------------
// blocks 0..63: w1t (16384), block 64,65: c1 (512), blocks 66..321: w2t (65536)
__global__ __launch_bounds__(256) void prep_weights_kernel(
    const float* __restrict__ Wa, const float* __restrict__ W1,
    const float* __restrict__ W2, const float* __restrict__ b_align)
{
    int gid = blockIdx.x * 256 + threadIdx.x;
    if (gid < 16384) {
        int k = gid >> 9, n = gid & 511;
        float acc = 0.f;
#pragma unroll 8
        for (int m = 0; m < 128; m++) acc = fmaf(Wa[k * 128 + m], W1[m * 512 + n], acc);
        __nv_bfloat16 h = __float2bfloat16(acc);
        g_w1t_h[n * 32 + k] = h;
        g_w1t_l[n * 32 + k] = __float2bfloat16(acc - __bfloat162float(h));
    } else if (gid < 16896) {
        int n = gid - 16384;
        float acc = 0.f;
#pragma unroll 8
        for (int m = 0; m < 128; m++) acc = fmaf(b_align[m], W1[m * 512 + n], acc);
        g_c1[n] = acc;
    } else {
        int idx = gid - 16896;          // 65536 items
        int n = idx >> 9, k = idx & 511;
        float v = W2[k * 128 + n];
        __nv_bfloat16 h = __float2bfloat16(v);
        g_w2t_h[n * 512 + k] = h;
        g_w2t_l[n * 512 + k] = __float2bfloat16(v - __bfloat162float(h));
    }
}

// ---------------- mega kernel: one CTA per graph ----------------
#define H1S 516                              // fp32 row stride of h1/o1 (pad 4)
#define SZ_H1   (64 * H1S * 4)               // 132096
#define OFF_SCR SZ_H1
#define SZ_SCR  49152
#define OFF_EMB (OFF_SCR + SZ_SCR)           // 181248
#define SZ_EMB  (2 * 64 * 80)                // 10240
#define MEGA_SMEM (OFF_EMB + SZ_EMB)         // 191488

#define CH_ARR  10240                        // 128 rows x 80 B
#define CH_BUF  20480                        // hi + lo

__global__ __launch_bounds__(256, 1) void mega_kernel(
    const float* __restrict__ emb, const int* __restrict__ eidx,
    const float* __restrict__ gl,
    const float* __restrict__ a_src1, const float* __restrict__ a_dst1,
    const float* __restrict__ b1,
    const float* __restrict__ a_src2, const float* __restrict__ a_dst2,
    const float* __restrict__ b2,
    const float* __restrict__ Wc1, const float* __restrict__ bc1,
    const float* __restrict__ Wc2, const float* __restrict__ bc2,
    float* __restrict__ outp, float* __restrict__ gate_out)
{
    extern __shared__ __align__(16) char smem[];
    float* s_h1 = (float*)smem;                                  // 64 x 516 fp32
    char*  s_scr = smem + OFF_SCR;                               // 48 KB scratch
    __nv_bfloat16* s_embh = (__nv_bfloat16*)(smem + OFF_EMB);    // 64 x 40 bf16 (80B rows)
    __nv_bfloat16* s_embl = s_embh + 64 * 40;

    __shared__ float s_ssrc[64], s_sdst[64], s_smax[64], s_ssum[64], s_gate[64];
    __shared__ float s_eprob[192];
    __shared__ int   s_eS[192], s_eT[192], s_order[192], s_startc[65], s_deg[64], s_cur[64];
    __shared__ float s_c1[512];
    __shared__ float s_g[128], s_hc[64];

    int b = blockIdx.x, t = threadIdx.x, lane = t & 31, w = t >> 5;
    int wm = w >> 1, wn = w & 1;                 // 4 x 2 warp grid (16 rows x 64 cols)
    int gr = lane >> 2, gc = (lane & 3) * 2;
    int node0 = b * 64;
    uint32_t sbScr = smem_to_u32(s_scr);
    uint32_t sbEmb = smem_to_u32(s_embh);

    // ---------- phase 0: gate, c1, edges + CSR, emb load/split ----------
    if (t < 64) {
        s_deg[t] = 0; s_cur[t] = 0;
        float gv = 1.0f / (1.0f + expf(-gl[t]));
        s_gate[t] = gv;
        if (b == 0 && gate_out != nullptr) gate_out[t] = gv;
    }
    s_c1[t] = g_c1[t]; s_c1[t + 256] = g_c1[t + 256];
    if (t < 192) {
        int s, tt;
        if (t < 128) { s = eidx[b * 128 + t] - node0; tt = eidx[E_EDGES + b * 128 + t] - node0; }
        else         { s = t - 128; tt = s; }
        s_eS[t] = s; s_eT[t] = tt;
    }
    // emb: 64 rows x 32 fp32 -> hi/lo bf16 (80B padded rows)
#pragma unroll
    for (int i = 0; i < 2; i++) {
        int f = t * 2 + i;            // 512 float4s
        int row = f >> 3, p = f & 7;
        float4 v = *(const float4*)(emb + (size_t)(node0 + row) * 32 + p * 4);
        __nv_bfloat16* ph = s_embh + row * 40 + p * 4;
        __nv_bfloat16* pl = s_embl + row * 40 + p * 4;
        __nv_bfloat16 h0 = __float2bfloat16(v.x), h1 = __float2bfloat16(v.y);
        __nv_bfloat16 h2 = __float2bfloat16(v.z), h3 = __float2bfloat16(v.w);
        ph[0] = h0; ph[1] = h1; ph[2] = h2; ph[3] = h3;
        pl[0] = __float2bfloat16(v.x - __bfloat162float(h0));
        pl[1] = __float2bfloat16(v.y - __bfloat162float(h1));
        pl[2] = __float2bfloat16(v.z - __bfloat162float(h2));
        pl[3] = __float2bfloat16(v.w - __bfloat162float(h3));
    }
    __syncthreads();
    if (t < 192) atomicAdd(&s_deg[s_eT[t]], 1);
    __syncthreads();
    if (t == 0) {
        int a = 0;
        for (int i = 0; i < 64; i++) { s_startc[i] = a; a += s_deg[i]; }
        s_startc[64] = a;
    }
    __syncthreads();
    if (t < 192) {
        int tt = s_eT[t];
        int pos = atomicAdd(&s_cur[tt], 1);
        s_order[s_startc[tt] + pos] = t;
    }

    // ---------- phase A: h1 = diag(gate) * (emb @ w1t^T + c1)  [64 x 512] ----------
    uint32_t aEmbH = sbEmb + (uint32_t)((wm * 16 + (lane & 15)) * 80 + (lane >> 4) * 16);
    uint32_t aEmbL = aEmbH + 5120;
    uint32_t boffL = (uint32_t)((wn * 64 + (lane & 15)) * 80 + (lane >> 4) * 16);

    __nv_bfloat16* w1th = g_w1t_h;
    __nv_bfloat16* w1tl = g_w1t_l;
    auto loadW1 = [&](int nc) {
        uint32_t dst = sbScr + (uint32_t)(nc & 1) * CH_BUF;
#pragma unroll
        for (int i = 0; i < 4; i++) {
            int item = t + i * 256;               // 1024 pieces
            int arr = item >> 9;                   // 0 hi, 1 lo
            int r = (item & 511) >> 2, p = item & 3;
            const __nv_bfloat16* src = (arr ? w1tl : w1th) + (size_t)(nc * 128 + r) * 32 + p * 8;
            cp16(dst + arr * CH_ARR + r * 80 + p * 16, src);
        }
    };

    loadW1(0); CP_COMMIT();
    for (int nc = 0; nc < 4; nc++) {
        if (nc + 1 < 4) { loadW1(nc + 1); CP_COMMIT(); CP_WAIT1(); }
        else            { CP_WAIT0(); }
        __syncthreads();

        uint32_t bufb = sbScr + (uint32_t)(nc & 1) * CH_BUF;
        float acc[8][4];
#pragma unroll
        for (int i = 0; i < 8; i++)
#pragma unroll
            for (int r = 0; r < 4; r++) acc[i][r] = 0.f;

#pragma unroll
        for (int kk = 0; kk < 2; kk++) {
            uint32_t ko = kk * 32;
            uint32_t ah[4], al[4], bh[4][4], bl[4][4];
            LDSM_X4(ah[0], ah[1], ah[2], ah[3], aEmbH + ko);
            LDSM_X4(al[0], al[1], al[2], al[3], aEmbL + ko);
#pragma unroll
            for (int s = 0; s < 4; s++) {
                LDSM_X4(bh[s][0], bh[s][1], bh[s][2], bh[s][3],
                        bufb + boffL + s * (16 * 80) + ko);
                LDSM_X4(bl[s][0], bl[s][1], bl[s][2], bl[s][3],
                        bufb + CH_ARR + boffL + s * (16 * 80) + ko);
            }
#pragma unroll
            for (int nt = 0; nt < 8; nt++) {
                int s = nt >> 1, o = nt & 1;
                MMA16816(acc[nt], ah, bh[s][o], bh[s][o + 2]);
                MMA16816(acc[nt], ah, bl[s][o], bl[s][o + 2]);
                MMA16816(acc[nt], al, bh[s][o], bh[s][o + 2]);
            }
        }
        // epilogue -> s_h1 with gate + c1
        int r0 = wm * 16 + gr;
        float g0 = s_gate[r0], g1 = s_gate[r0 + 8];
        int n0 = nc * 128;
#pragma unroll
        for (int nt = 0; nt < 8; nt++) {
            int n = n0 + wn * 64 + nt * 8 + gc;
            s_h1[r0 * H1S + n]           = g0 * (acc[nt][0] + s_c1[n]);
            s_h1[r0 * H1S + n + 1]       = g0 * (acc[nt][1] + s_c1[n + 1]);
            s_h1[(r0 + 8) * H1S + n]     = g1 * (acc[nt][2] + s_c1[n]);
            s_h1[(r0 + 8) * H1S + n + 1] = g1 * (acc[nt][3] + s_c1[n + 1]);
        }
        __syncthreads();
    }

    // ---------- phase B: GAT layer 1, 4 heads, in-place on s_h1 ----------
    float* s_tmp = (float*)s_scr;          // 64 x 128 fp32 head staging
    for (int h = 0; h < HEADS; h++) {
        int hoff = h * 128;
        if (t < 64) { s_smax[t] = -1e30f; s_ssum[t] = 0.f; }
        __syncthreads();
        // node scores
        {
            float a0 = __ldg(&a_src1[hoff + lane * 4]);
            float a1 = __ldg(&a_src1[hoff + lane * 4 + 1]);
            float a2 = __ldg(&a_src1[hoff + lane * 4 + 2]);
            float a3 = __ldg(&a_src1[hoff + lane * 4 + 3]);
            float d0 = __ldg(&a_dst1[hoff + lane * 4]);
            float d1 = __ldg(&a_dst1[hoff + lane * 4 + 1]);
            float d2 = __ldg(&a_dst1[hoff + lane * 4 + 2]);
            float d3 = __ldg(&a_dst1[hoff + lane * 4 + 3]);
#pragma unroll
            for (int j = 0; j < 8; j++) {
                int i = w * 8 + j;
                float4 hv = *(const float4*)(s_h1 + i * H1S + hoff + lane * 4);
                float s1 = hv.x * a0 + hv.y * a1 + hv.z * a2 + hv.w * a3;
                float s2 = hv.x * d0 + hv.y * d1 + hv.z * d2 + hv.w * d3;
#pragma unroll
                for (int off = 16; off > 0; off >>= 1) {
                    s1 += __shfl_xor_sync(0xffffffffu, s1, off);
                    s2 += __shfl_xor_sync(0xffffffffu, s2, off);
                }
                if (lane == 0) { s_ssrc[i] = s1; s_sdst[i] = s2; }
            }
        }
        __syncthreads();
        if (t < 192) {
            float sc = s_ssrc[s_eS[t]] + s_sdst[s_eT[t]];
            sc = sc > 0.f ? sc : 0.2f * sc;
            s_eprob[t] = sc;
            atomicMaxFloatS(&s_smax[s_eT[t]], sc);
        }
        __syncthreads();
        if (t < 192) {
            float p = expf(s_eprob[t] - s_smax[s_eT[t]]);
            s_eprob[t] = p;
            atomicAdd(&s_ssum[s_eT[t]], p);
        }
        __syncthreads();
        // aggregate -> s_tmp
        {
            int d = t & 127, half = t >> 7;
            float bd = __ldg(&b1[hoff + d]);
            for (int tt = half * 32; tt < half * 32 + 32; tt++) {
                float acc = 0.f;
                int s0 = s_startc[tt], s1 = s_startc[tt + 1];
                for (int k = s0; k < s1; k++) {
                    int e = s_order[k];
                    acc = fmaf(s_eprob[e], s_h1[s_eS[e] * H1S + hoff + d], acc);
                }
                float val = acc / (s_ssum[tt] + 1e-16f) + bd;
                val = val > 0.f ? val : (expf(val) - 1.f);    // elu
                s_tmp[tt * 128 + d] = val;
            }
        }
        __syncthreads();
        // copy back over h1 head slice
        for (int idx = t; idx < 8192; idx += 256) {
            int row = idx >> 7, d2 = idx & 127;
            s_h1[row * H1S + hoff + d2] = s_tmp[idx];
        }
        __syncthreads();
    }

    // ---------- phase C: h2 = o1 @ w2t^T   [64 x 128], K = 512 ----------
    __nv_bfloat16* w2th = g_w2t_h;
    __nv_bfloat16* w2tl = g_w2t_l;
    auto loadW2 = [&](int kc) {
        uint32_t dst = sbScr + (uint32_t)(kc & 1) * CH_BUF;
#pragma unroll
        for (int i = 0; i < 4; i++) {
            int item = t + i * 256;
            int arr = item >> 9;
            int r = (item & 511) >> 2, p = item & 3;
            const __nv_bfloat16* src = (arr ? w2tl : w2th) + (size_t)r * 512 + kc * 32 + p * 8;
            cp16(dst + arr * CH_ARR + r * 80 + p * 16, src);
        }
    };

    float acc2[8][4];
#pragma unroll
    for (int i = 0; i < 8; i++)
#pragma unroll
        for (int r = 0; r < 4; r++) acc2[i][r] = 0.f;

    int r0 = wm * 16 + gr;
    const float* A0 = s_h1 + r0 * H1S;
    const float* A1 = s_h1 + (r0 + 8) * H1S;

    loadW2(0); CP_COMMIT();
    for (int kc = 0; kc < 16; kc++) {
        if (kc + 1 < 16) { loadW2(kc + 1); CP_COMMIT(); CP_WAIT1(); }
        else             { CP_WAIT0(); }
        __syncthreads();

        uint32_t bufb = sbScr + (uint32_t)(kc & 1) * CH_BUF;
#pragma unroll
        for (int kk = 0; kk < 2; kk++) {
            int c0 = kc * 32 + kk * 16 + gc;
            float2 v0a = *(const float2*)(A0 + c0);
            float2 v0b = *(const float2*)(A0 + c0 + 8);
            float2 v1a = *(const float2*)(A1 + c0);
            float2 v1b = *(const float2*)(A1 + c0 + 8);
            uint32_t ah[4], al[4];
            split2(v0a.x, v0a.y, ah[0], al[0]);
            split2(v1a.x, v1a.y, ah[1], al[1]);
            split2(v0b.x, v0b.y, ah[2], al[2]);
            split2(v1b.x, v1b.y, ah[3], al[3]);

            uint32_t ko = kk * 32;
            uint32_t bh[4][4], bl[4][4];
#pragma unroll
            for (int s = 0; s < 4; s++) {
                LDSM_X4(bh[s][0], bh[s][1], bh[s][2], bh[s][3],
                        bufb + boffL + s * (16 * 80) + ko);
                LDSM_X4(bl[s][0], bl[s][1], bl[s][2], bl[s][3],
                        bufb + CH_ARR + boffL + s * (16 * 80) + ko);
            }
#pragma unroll
            for (int nt = 0; nt < 8; nt++) {
                int s = nt >> 1, o = nt & 1;
                MMA16816(acc2[nt], ah, bh[s][o], bh[s][o + 2]);
                MMA16816(acc2[nt], ah, bl[s][o], bl[s][o + 2]);
                MMA16816(acc2[nt], al, bh[s][o], bh[s][o + 2]);
            }
        }
        __syncthreads();
    }
    // write h2 into scratch (buffers dead)
    float* s_h2 = (float*)s_scr;
#pragma unroll
    for (int nt = 0; nt < 8; nt++) {
        int col = wn * 64 + nt * 8 + gc;
        s_h2[r0 * 128 + col]           = acc2[nt][0];
        s_h2[r0 * 128 + col + 1]       = acc2[nt][1];
        s_h2[(r0 + 8) * 128 + col]     = acc2[nt][2];
        s_h2[(r0 + 8) * 128 + col + 1] = acc2[nt][3];
    }
    __syncthreads();

    // ---------- phase D: GAT layer 2 (1 head) -> o2 in s_h1 (stride 128) ----------
    float* s_o2 = s_h1;
    if (t < 64) { s_smax[t] = -1e30f; s_ssum[t] = 0.f; }
    __syncthreads();
    {
        float a0 = __ldg(&a_src2[lane * 4]);
        float a1 = __ldg(&a_src2[lane * 4 + 1]);
        float a2 = __ldg(&a_src2[lane * 4 + 2]);
        float a3 = __ldg(&a_src2[lane * 4 + 3]);
        float d0 = __ldg(&a_dst2[lane * 4]);
        float d1 = __ldg(&a_dst2[lane * 4 + 1]);
        float d2 = __ldg(&a_dst2[lane * 4 + 2]);
        float d3 = __ldg(&a_dst2[lane * 4 + 3]);
#pragma unroll
        for (int j = 0; j < 8; j++) {
            int i = w * 8 + j;
            float4 hv = *(const float4*)(s_h2 + i * 128 + lane * 4);
            float s1 = hv.x * a0 + hv.y * a1 + hv.z * a2 + hv.w * a3;
            float s2 = hv.x * d0 + hv.y * d1 + hv.z * d2 + hv.w * d3;
#pragma unroll
            for (int off = 16; off > 0; off >>= 1) {
                s1 += __shfl_xor_sync(0xffffffffu, s1, off);
                s2 += __shfl_xor_sync(0xffffffffu, s2, off);
            }
            if (lane == 0) { s_ssrc[i] = s1; s_sdst[i] = s2; }
        }
    }
    __syncthreads();
    if (t < 192) {
        float sc = s_ssrc[s_eS[t]] + s_sdst[s_eT[t]];
        sc = sc > 0.f ? sc : 0.2f * sc;
        s_eprob[t] = sc;
        atomicMaxFloatS(&s_smax[s_eT[t]], sc);
    }
    __syncthreads();
    if (t < 192) {
        float p = expf(s_eprob[t] - s_smax[s_eT[t]]);
        s_eprob[t] = p;
        atomicAdd(&s_ssum[s_eT[t]], p);
    }
    __syncthreads();
    {
        int d = t & 127, half = t >> 7;
        float bd = __ldg(&b2[d]);
        for (int tt = half * 32; tt < half * 32 + 32; tt++) {
            float acc = 0.f;
            int s0 = s_startc[tt], s1 = s_startc[tt + 1];
            for (int k = s0; k < s1; k++) {
                int e = s_order[k];
                acc = fmaf(s_eprob[e], s_h2[s_eS[e] * 128 + d], acc);
            }
            s_o2[tt * 128 + d] = acc / (s_ssum[tt] + 1e-16f) + bd;
        }
    }
    __syncthreads();

    // ---------- phase E: mean pool + classifier ----------
    if (t < 128) {
        float acc = 0.f;
#pragma unroll 8
        for (int i = 0; i < 64; i++) acc += s_o2[i * 128 + t];
        s_g[t] = acc * (1.0f / 64.0f);
    }
    __syncthreads();
    if (t < 64) {
        float a = __ldg(&bc1[t]);
#pragma unroll 8
        for (int d = 0; d < 128; d++) a = fmaf(s_g[d], __ldg(&Wc1[d * 64 + t]), a);
        s_hc[t] = a > 0.f ? a : 0.01f * a;
    }
    __syncthreads();
    if (t < 16) {
        float a = __ldg(&bc2[t]);
#pragma unroll 8
        for (int j = 0; j < 64; j++) a = fmaf(s_hc[j], __ldg(&Wc2[j * 16 + t]), a);
        outp[(size_t)b * 16 + t] = a;
    }
}

// ---------------- launch ----------------
extern "C" void kernel_launch(void* const* d_in, const int* in_sizes, int n_in,
                              void* d_out, int out_size)
{
    const float* emb         = (const float*)d_in[0];
    const int*   edge_index  = (const int*)d_in[1];
    const float* W_align     = (const float*)d_in[3];
    const float* b_align     = (const float*)d_in[4];
    const float* gate_logits = (const float*)d_in[5];
    const float* W1          = (const float*)d_in[6];
    const float* a_src1      = (const float*)d_in[7];
    const float* a_dst1      = (const float*)d_in[8];
    const float* b1          = (const float*)d_in[9];
    const float* W2          = (const float*)d_in[10];
    const float* a_src2      = (const float*)d_in[11];
    const float* a_dst2      = (const float*)d_in[12];
    const float* b2          = (const float*)d_in[13];
    const float* Wc1         = (const float*)d_in[14];
    const float* bc1         = (const float*)d_in[15];
    const float* Wc2         = (const float*)d_in[16];
    const float* bc2         = (const float*)d_in[17];
    float* out = (float*)d_out;

    cudaFuncSetAttribute(mega_kernel, cudaFuncAttributeMaxDynamicSharedMemorySize, MEGA_SMEM);

    float* gate_out = (out_size >= 64) ? (out + (out_size - 64)) : nullptr;

    // 1) weight prep (one small launch)
    prep_weights_kernel<<<322, 256>>>(W_align, W1, W2, b_align);

    // 2) fused per-graph pipeline
    mega_kernel<<<B_GRAPHS, 256, MEGA_SMEM>>>(
        emb, edge_index, gate_logits,
        a_src1, a_dst1, b1, a_src2, a_dst2, b2,
        Wc1, bc1, Wc2, bc2, out, gate_out);
}

// round 5
// speedup vs baseline: 1.6837x; 1.6837x over previous
#include <cuda_runtime.h>
#include <cuda_bf16.h>
#include <math.h>
#include <cstdint>

// ---------------- problem constants ----------------
#define B_GRAPHS 2048
#define F_NODES  64
#define D_IN     32
#define HDIM     128
#define HEADS    4
#define NC       16
#define EPG      128
#define N_NODES  (B_GRAPHS * F_NODES)        // 131072
#define E_EDGES  (B_GRAPHS * EPG)            // 262144

// ---------------- device-global scratch ----------------
__device__ __nv_bfloat16 g_w1t_h[512 * 32];   // (Wa@W1)^T  [n][k]
__device__ __nv_bfloat16 g_w1t_l[512 * 32];
__device__ float         g_c1[512];           // b_align @ W1
__device__ __nv_bfloat16 g_w2t_h[128 * 512];  // W2^T  [n][k]
__device__ __nv_bfloat16 g_w2t_l[128 * 512];
__device__ __nv_bfloat16 g_o1h[(size_t)N_NODES * 512];
__device__ __nv_bfloat16 g_o1l[(size_t)N_NODES * 512];

// ---------------- PTX helpers (sm_80+; no tcgen05 — ptxas targets compute_103) ----------------
__device__ __forceinline__ uint32_t smem_to_u32(const void* p) {
    uint32_t a;
    asm("{ .reg .u64 tmp; cvta.to.shared.u64 tmp, %1; cvt.u32.u64 %0, tmp; }" : "=r"(a) : "l"(p));
    return a;
}
__device__ __forceinline__ void cp16(uint32_t saddr, const void* g) {
    asm volatile("cp.async.cg.shared.global [%0], [%1], 16;"
                 :: "r"(saddr), "l"(g) : "memory");
}
#define CP_COMMIT() asm volatile("cp.async.commit_group;" ::: "memory")
#define CP_WAIT0()  asm volatile("cp.async.wait_group 0;" ::: "memory")
#define CP_WAIT1()  asm volatile("cp.async.wait_group 1;" ::: "memory")

#define LDSM_X4(r0, r1, r2, r3, addr) \
    asm volatile("ldmatrix.sync.aligned.m8n8.x4.shared.b16 {%0,%1,%2,%3}, [%4];" \
                 : "=r"(r0), "=r"(r1), "=r"(r2), "=r"(r3) : "r"(addr))

#define MMA16816(d, a, b0, b1) \
    asm volatile("mma.sync.aligned.m16n8k16.row.col.f32.bf16.bf16.f32 " \
                 "{%0,%1,%2,%3}, {%4,%5,%6,%7}, {%8,%9}, {%0,%1,%2,%3};" \
                 : "+f"((d)[0]), "+f"((d)[1]), "+f"((d)[2]), "+f"((d)[3]) \
                 : "r"((a)[0]), "r"((a)[1]), "r"((a)[2]), "r"((a)[3]), "r"(b0), "r"(b1))

__device__ __forceinline__ void atomicMaxFloatS(float* addr, float val) {
    int* ai = (int*)addr;
    int old = *ai;
    while (__int_as_float(old) < val) {
        int assumed = old;
        old = atomicCAS(ai, assumed, __float_as_int(val));
        if (old == assumed) break;
    }
}

// ---------------- prep: fused/transposed weights + gate, single launch ----------------
__global__ __launch_bounds__(256) void prep_weights_kernel(
    const float* __restrict__ Wa, const float* __restrict__ W1,
    const float* __restrict__ W2, const float* __restrict__ b_align,
    const float* __restrict__ gl, float* __restrict__ gate_out)
{
    int gid = blockIdx.x * 256 + threadIdx.x;
    if (gid < 16384) {
        int k = gid >> 9, n = gid & 511;
        float acc = 0.f;
#pragma unroll 8
        for (int m = 0; m < 128; m++) acc = fmaf(Wa[k * 128 + m], W1[m * 512 + n], acc);
        __nv_bfloat16 h = __float2bfloat16(acc);
        g_w1t_h[n * 32 + k] = h;
        g_w1t_l[n * 32 + k] = __float2bfloat16(acc - __bfloat162float(h));
    } else if (gid < 16896) {
        int n = gid - 16384;
        float acc = 0.f;
#pragma unroll 8
        for (int m = 0; m < 128; m++) acc = fmaf(b_align[m], W1[m * 512 + n], acc);
        g_c1[n] = acc;
    } else if (gid < 82432) {
        int idx = gid - 16896;          // 65536 items
        int n = idx >> 9, k = idx & 511;
        float v = W2[k * 128 + n];
        __nv_bfloat16 h = __float2bfloat16(v);
        g_w2t_h[n * 512 + k] = h;
        g_w2t_l[n * 512 + k] = __float2bfloat16(v - __bfloat162float(h));
    } else if (gid < 82496) {
        int f = gid - 82432;
        if (gate_out != nullptr) gate_out[f] = 1.0f / (1.0f + expf(-gl[f]));
    }
}

// ---------------- kernel A: per (graph, head) — GEMM1 + GAT1 ----------------
// smem dyn: [0,5120) embh | [5120,10240) embl | [10240,44032) union{ w1t h/l , h1 fp32 64x132 }
#define KA_SMEM 44032

__global__ __launch_bounds__(128, 4) void gemm1_gat1_kernel(
    const float* __restrict__ emb, const int* __restrict__ eidx,
    const float* __restrict__ gl,
    const float* __restrict__ a_src1, const float* __restrict__ a_dst1,
    const float* __restrict__ b1)
{
    extern __shared__ __align__(16) char smem[];
    __nv_bfloat16* s_embh = (__nv_bfloat16*)smem;
    __nv_bfloat16* s_embl = (__nv_bfloat16*)(smem + 5120);
    float* s_h1 = (float*)(smem + 10240);        // stride 132 fp32
    uint32_t sb = smem_to_u32(smem);

    __shared__ float s_gate[64], s_ssrc[64], s_sdst[64], s_smax[64], s_ssum[64], s_c1[128];
    __shared__ float s_eprob[192];
    __shared__ int   s_eS[192], s_eT[192], s_order[192], s_startc[65], s_deg[64], s_cur[64];

    int h = blockIdx.x, b = blockIdx.y;
    int hoff = h * 128;
    int t = threadIdx.x, lane = t & 31, w = t >> 5;
    int node0 = b * 64;

    // kick w1t head-slice loads first (overlaps phase 0)
#pragma unroll
    for (int i = 0; i < 8; i++) {
        int item = t + i * 128;                  // 1024 pieces
        int arr = item >> 9;
        int r = (item & 511) >> 2, p = item & 3;
        const __nv_bfloat16* src = (arr ? g_w1t_l : g_w1t_h) + (size_t)(hoff + r) * 32 + p * 8;
        cp16(sb + 10240 + arr * 10240 + r * 80 + p * 16, src);
    }
    CP_COMMIT();

    if (t < 64) {
        s_deg[t] = 0; s_cur[t] = 0;
        s_gate[t] = 1.0f / (1.0f + expf(-gl[t]));
        s_smax[t] = -1e30f; s_ssum[t] = 0.f;
    }
    s_c1[t] = g_c1[hoff + t];
    // edges (128 real + 64 self-loops)
    s_eS[t] = eidx[b * 128 + t] - node0;
    s_eT[t] = eidx[E_EDGES + b * 128 + t] - node0;
    if (t < 64) { s_eS[128 + t] = t; s_eT[128 + t] = t; }
    // emb -> hi/lo bf16 smem (80B rows)
#pragma unroll
    for (int i = 0; i < 4; i++) {
        int f = t + i * 128;                     // 512 float4
        int row = f >> 3, p = f & 7;
        float4 v = *(const float4*)(emb + (size_t)(node0 + row) * 32 + p * 4);
        __nv_bfloat16* ph = s_embh + row * 40 + p * 4;
        __nv_bfloat16* pl = s_embl + row * 40 + p * 4;
        __nv_bfloat16 h0 = __float2bfloat16(v.x), h1v = __float2bfloat16(v.y);
        __nv_bfloat16 h2 = __float2bfloat16(v.z), h3 = __float2bfloat16(v.w);
        ph[0] = h0; ph[1] = h1v; ph[2] = h2; ph[3] = h3;
        pl[0] = __float2bfloat16(v.x - __bfloat162float(h0));
        pl[1] = __float2bfloat16(v.y - __bfloat162float(h1v));
        pl[2] = __float2bfloat16(v.z - __bfloat162float(h2));
        pl[3] = __float2bfloat16(v.w - __bfloat162float(h3));
    }
    __syncthreads();
    for (int e = t; e < 192; e += 128) atomicAdd(&s_deg[s_eT[e]], 1);
    __syncthreads();
    if (t == 0) {
        int a = 0;
        for (int i = 0; i < 64; i++) { s_startc[i] = a; a += s_deg[i]; }
        s_startc[64] = a;
    }
    __syncthreads();
    for (int e = t; e < 192; e += 128) {
        int tt = s_eT[e];
        int pos = atomicAdd(&s_cur[tt], 1);
        s_order[s_startc[tt] + pos] = e;
    }

    CP_WAIT0();
    __syncthreads();

    // ---- GEMM1: 4 warps, warp w = 16 rows, all 128 cols; K=32, 3-pass hi/lo ----
    float acc[16][4];
#pragma unroll
    for (int i = 0; i < 16; i++)
#pragma unroll
        for (int r = 0; r < 4; r++) acc[i][r] = 0.f;

    uint32_t aH = sb + (uint32_t)((w * 16 + (lane & 15)) * 80 + (lane >> 4) * 16);
    uint32_t aL = aH + 5120;
    uint32_t boff = (uint32_t)((lane & 15) * 80 + (lane >> 4) * 16);
    uint32_t bH0 = sb + 10240 + boff, bL0 = sb + 20480 + boff;

#pragma unroll
    for (int kk = 0; kk < 2; kk++) {
        uint32_t ko = kk * 32;
        uint32_t ah[4], al[4];
        LDSM_X4(ah[0], ah[1], ah[2], ah[3], aH + ko);
        LDSM_X4(al[0], al[1], al[2], al[3], aL + ko);
#pragma unroll
        for (int s = 0; s < 8; s++) {
            uint32_t bh[4], bl[4];
            LDSM_X4(bh[0], bh[1], bh[2], bh[3], bH0 + s * 1280 + ko);
            LDSM_X4(bl[0], bl[1], bl[2], bl[3], bL0 + s * 1280 + ko);
#pragma unroll
            for (int o = 0; o < 2; o++) {
                int nt = s * 2 + o;
                MMA16816(acc[nt], ah, bh[o], bh[o + 2]);
                MMA16816(acc[nt], ah, bl[o], bl[o + 2]);
                MMA16816(acc[nt], al, bh[o], bh[o + 2]);
            }
        }
    }
    __syncthreads();          // w1t region now dead -> reuse as h1

    // epilogue: h1 = gate * (acc + c1)
    int gr = lane >> 2, gc = (lane & 3) * 2;
    int r0 = w * 16 + gr;
    float g0 = s_gate[r0], g1 = s_gate[r0 + 8];
#pragma unroll
    for (int nt = 0; nt < 16; nt++) {
        int col = nt * 8 + gc;
        s_h1[r0 * 132 + col]           = g0 * (acc[nt][0] + s_c1[col]);
        s_h1[r0 * 132 + col + 1]       = g0 * (acc[nt][1] + s_c1[col + 1]);
        s_h1[(r0 + 8) * 132 + col]     = g1 * (acc[nt][2] + s_c1[col]);
        s_h1[(r0 + 8) * 132 + col + 1] = g1 * (acc[nt][3] + s_c1[col + 1]);
    }
    __syncthreads();

    // ---- GAT1 on this head ----
    {
        float a0 = __ldg(&a_src1[hoff + lane * 4]);
        float a1 = __ldg(&a_src1[hoff + lane * 4 + 1]);
        float a2 = __ldg(&a_src1[hoff + lane * 4 + 2]);
        float a3 = __ldg(&a_src1[hoff + lane * 4 + 3]);
        float d0 = __ldg(&a_dst1[hoff + lane * 4]);
        float d1 = __ldg(&a_dst1[hoff + lane * 4 + 1]);
        float d2 = __ldg(&a_dst1[hoff + lane * 4 + 2]);
        float d3 = __ldg(&a_dst1[hoff + lane * 4 + 3]);
#pragma unroll
        for (int i = w; i < 64; i += 4) {
            float4 hv = *(const float4*)(s_h1 + i * 132 + lane * 4);
            float s1 = hv.x * a0 + hv.y * a1 + hv.z * a2 + hv.w * a3;
            float s2 = hv.x * d0 + hv.y * d1 + hv.z * d2 + hv.w * d3;
#pragma unroll
            for (int off = 16; off > 0; off >>= 1) {
                s1 += __shfl_xor_sync(0xffffffffu, s1, off);
                s2 += __shfl_xor_sync(0xffffffffu, s2, off);
            }
            if (lane == 0) { s_ssrc[i] = s1; s_sdst[i] = s2; }
        }
    }
    __syncthreads();
    for (int e = t; e < 192; e += 128) {
        float sc = s_ssrc[s_eS[e]] + s_sdst[s_eT[e]];
        sc = sc > 0.f ? sc : 0.2f * sc;
        s_eprob[e] = sc;
        atomicMaxFloatS(&s_smax[s_eT[e]], sc);
    }
    __syncthreads();
    for (int e = t; e < 192; e += 128) {
        float p = expf(s_eprob[e] - s_smax[s_eT[e]]);
        s_eprob[e] = p;
        atomicAdd(&s_ssum[s_eT[e]], p);
    }
    __syncthreads();
    // aggregate + bias + elu -> o1 (bf16 hi/lo) global
    {
        int d = t;
        float bd = __ldg(&b1[hoff + d]);
        for (int tt = 0; tt < 64; tt++) {
            float a = 0.f;
            int s0 = s_startc[tt], s1 = s_startc[tt + 1];
            for (int k = s0; k < s1; k++) {
                int e = s_order[k];
                a = fmaf(s_eprob[e], s_h1[s_eS[e] * 132 + d], a);
            }
            float val = a / (s_ssum[tt] + 1e-16f) + bd;
            val = val > 0.f ? val : (expf(val) - 1.f);
            __nv_bfloat16 hi = __float2bfloat16(val);
            size_t o = (size_t)(node0 + tt) * 512 + hoff + d;
            g_o1h[o] = hi;
            g_o1l[o] = __float2bfloat16(val - __bfloat162float(hi));
        }
    }
}

// ---------------- kernel B: per graph — GEMM2 + GAT2 + pool + classifier ----------------
// smem dyn: [0,33792) h2 fp32 64x132 | [33792,95232) chunk buffers (2 x 30720)
//   buffer: o1h 5120 | o1l 5120 | w2h 10240 | w2l 10240   (80B rows)
//   after GEMM: o2 fp32 64x128 overlays the buffer region
#define KB_SMEM 95232

__global__ __launch_bounds__(256, 2) void gemm2_rest_kernel(
    const int* __restrict__ eidx,
    const float* __restrict__ a_src2, const float* __restrict__ a_dst2,
    const float* __restrict__ b2,
    const float* __restrict__ Wc1, const float* __restrict__ bc1,
    const float* __restrict__ Wc2, const float* __restrict__ bc2,
    float* __restrict__ outp)
{
    extern __shared__ __align__(16) char smem[];
    float* s_h2 = (float*)smem;                   // stride 132
    char*  s_buf = smem + 33792;
    float* s_o2 = (float*)(smem + 33792);         // stride 128, after GEMM
    uint32_t sbBuf = smem_to_u32(s_buf);

    __shared__ float s_ssrc[64], s_sdst[64], s_smax[64], s_ssum[64];
    __shared__ float s_eprob[192];
    __shared__ int   s_eS[192], s_eT[192], s_order[192], s_startc[65], s_deg[64], s_cur[64];
    __shared__ float s_g[128], s_hc[64];

    int b = blockIdx.x, t = threadIdx.x, lane = t & 31, w = t >> 5;
    int wm = w >> 1, wn = w & 1;
    int node0 = b * 64;

    auto loadChunk = [&](int kc) {
        uint32_t dst = sbBuf + (uint32_t)(kc & 1) * 30720;
#pragma unroll
        for (int i = 0; i < 6; i++) {
            int item = t + i * 256;               // 1536 pieces
            if (item < 512) {
                int arr = item >> 8;
                int r = (item & 255) >> 2, p = item & 3;
                const __nv_bfloat16* src =
                    (arr ? g_o1l : g_o1h) + (size_t)(node0 + r) * 512 + kc * 32 + p * 8;
                cp16(dst + arr * 5120 + r * 80 + p * 16, src);
            } else {
                int idx = item - 512;             // 1024 pieces
                int arr = idx >> 9;
                int r = (idx & 511) >> 2, p = idx & 3;
                const __nv_bfloat16* src =
                    (arr ? g_w2t_l : g_w2t_h) + (size_t)r * 512 + kc * 32 + p * 8;
                cp16(dst + 10240 + arr * 10240 + r * 80 + p * 16, src);
            }
        }
    };

    loadChunk(0); CP_COMMIT();

    // CSR / init (overlaps chunk-0 load)
    if (t < 64) {
        s_deg[t] = 0; s_cur[t] = 0;
        s_smax[t] = -1e30f; s_ssum[t] = 0.f;
    }
    if (t < 192) {
        int s, tt;
        if (t < 128) { s = eidx[b * 128 + t] - node0; tt = eidx[E_EDGES + b * 128 + t] - node0; }
        else         { s = t - 128; tt = s; }
        s_eS[t] = s; s_eT[t] = tt;
    }
    __syncthreads();
    if (t < 192) atomicAdd(&s_deg[s_eT[t]], 1);
    __syncthreads();
    if (t == 0) {
        int a = 0;
        for (int i = 0; i < 64; i++) { s_startc[i] = a; a += s_deg[i]; }
        s_startc[64] = a;
    }
    __syncthreads();
    if (t < 192) {
        int tt = s_eT[t];
        int pos = atomicAdd(&s_cur[tt], 1);
        s_order[s_startc[tt] + pos] = t;
    }

    // ---- GEMM2: h2 = o1 @ w2t^T, K=512 in 16 chunks, 3-pass hi/lo ----
    float acc[8][4];
#pragma unroll
    for (int i = 0; i < 8; i++)
#pragma unroll
        for (int r = 0; r < 4; r++) acc[i][r] = 0.f;

    uint32_t aoff = (uint32_t)((wm * 16 + (lane & 15)) * 80 + (lane >> 4) * 16);
    uint32_t boff = (uint32_t)((wn * 64 + (lane & 15)) * 80 + (lane >> 4) * 16);

    for (int kc = 0; kc < 16; kc++) {
        if (kc + 1 < 16) { loadChunk(kc + 1); CP_COMMIT(); CP_WAIT1(); }
        else             { CP_WAIT0(); }
        __syncthreads();

        uint32_t bufb = sbBuf + (uint32_t)(kc & 1) * 30720;
#pragma unroll
        for (int kk = 0; kk < 2; kk++) {
            uint32_t ko = kk * 32;
            uint32_t ah[4], al[4];
            LDSM_X4(ah[0], ah[1], ah[2], ah[3], bufb + aoff + ko);
            LDSM_X4(al[0], al[1], al[2], al[3], bufb + 5120 + aoff + ko);
#pragma unroll
            for (int s = 0; s < 4; s++) {
                uint32_t bh[4], bl[4];
                LDSM_X4(bh[0], bh[1], bh[2], bh[3], bufb + 10240 + boff + s * 1280 + ko);
                LDSM_X4(bl[0], bl[1], bl[2], bl[3], bufb + 20480 + boff + s * 1280 + ko);
#pragma unroll
                for (int o = 0; o < 2; o++) {
                    int nt = s * 2 + o;
                    MMA16816(acc[nt], ah, bh[o], bh[o + 2]);
                    MMA16816(acc[nt], ah, bl[o], bl[o + 2]);
                    MMA16816(acc[nt], al, bh[o], bh[o + 2]);
                }
            }
        }
        __syncthreads();
    }

    // write h2
    int gr = lane >> 2, gc = (lane & 3) * 2;
    int r0 = wm * 16 + gr;
#pragma unroll
    for (int nt = 0; nt < 8; nt++) {
        int col = wn * 64 + nt * 8 + gc;
        s_h2[r0 * 132 + col]           = acc[nt][0];
        s_h2[r0 * 132 + col + 1]       = acc[nt][1];
        s_h2[(r0 + 8) * 132 + col]     = acc[nt][2];
        s_h2[(r0 + 8) * 132 + col + 1] = acc[nt][3];
    }
    __syncthreads();

    // ---- GAT2 (1 head) ----
    {
        float a0 = __ldg(&a_src2[lane * 4]);
        float a1 = __ldg(&a_src2[lane * 4 + 1]);
        float a2 = __ldg(&a_src2[lane * 4 + 2]);
        float a3 = __ldg(&a_src2[lane * 4 + 3]);
        float d0 = __ldg(&a_dst2[lane * 4]);
        float d1 = __ldg(&a_dst2[lane * 4 + 1]);
        float d2 = __ldg(&a_dst2[lane * 4 + 2]);
        float d3 = __ldg(&a_dst2[lane * 4 + 3]);
#pragma unroll
        for (int i = w; i < 64; i += 8) {
            float4 hv = *(const float4*)(s_h2 + i * 132 + lane * 4);
            float s1 = hv.x * a0 + hv.y * a1 + hv.z * a2 + hv.w * a3;
            float s2 = hv.x * d0 + hv.y * d1 + hv.z * d2 + hv.w * d3;
#pragma unroll
            for (int off = 16; off > 0; off >>= 1) {
                s1 += __shfl_xor_sync(0xffffffffu, s1, off);
                s2 += __shfl_xor_sync(0xffffffffu, s2, off);
            }
            if (lane == 0) { s_ssrc[i] = s1; s_sdst[i] = s2; }
        }
    }
    __syncthreads();
    if (t < 192) {
        float sc = s_ssrc[s_eS[t]] + s_sdst[s_eT[t]];
        sc = sc > 0.f ? sc : 0.2f * sc;
        s_eprob[t] = sc;
        atomicMaxFloatS(&s_smax[s_eT[t]], sc);
    }
    __syncthreads();
    if (t < 192) {
        float p = expf(s_eprob[t] - s_smax[s_eT[t]]);
        s_eprob[t] = p;
        atomicAdd(&s_ssum[s_eT[t]], p);
    }
    __syncthreads();
    {
        int d = t & 127, half = t >> 7;
        float bd = __ldg(&b2[d]);
        for (int tt = half * 32; tt < half * 32 + 32; tt++) {
            float a = 0.f;
            int s0 = s_startc[tt], s1 = s_startc[tt + 1];
            for (int k = s0; k < s1; k++) {
                int e = s_order[k];
                a = fmaf(s_eprob[e], s_h2[s_eS[e] * 132 + d], a);
            }
            s_o2[tt * 128 + d] = a / (s_ssum[tt] + 1e-16f) + bd;
        }
    }
    __syncthreads();

    // ---- mean pool + classifier ----
    if (t < 128) {
        float a = 0.f;
#pragma unroll 8
        for (int i = 0; i < 64; i++) a += s_o2[i * 128 + t];
        s_g[t] = a * (1.0f / 64.0f);
    }
    __syncthreads();
    if (t < 64) {
        float a = __ldg(&bc1[t]);
#pragma unroll 8
        for (int d = 0; d < 128; d++) a = fmaf(s_g[d], __ldg(&Wc1[d * 64 + t]), a);
        s_hc[t] = a > 0.f ? a : 0.01f * a;
    }
    __syncthreads();
    if (t < 16) {
        float a = __ldg(&bc2[t]);
#pragma unroll 8
        for (int j = 0; j < 64; j++) a = fmaf(s_hc[j], __ldg(&Wc2[j * 16 + t]), a);
        outp[(size_t)b * 16 + t] = a;
    }
}

// ---------------- launch ----------------
extern "C" void kernel_launch(void* const* d_in, const int* in_sizes, int n_in,
                              void* d_out, int out_size)
{
    const float* emb         = (const float*)d_in[0];
    const int*   edge_index  = (const int*)d_in[1];
    const float* W_align     = (const float*)d_in[3];
    const float* b_align     = (const float*)d_in[4];
    const float* gate_logits = (const float*)d_in[5];
    const float* W1          = (const float*)d_in[6];
    const float* a_src1      = (const float*)d_in[7];
    const float* a_dst1      = (const float*)d_in[8];
    const float* b1          = (const float*)d_in[9];
    const float* a_src2      = (const float*)d_in[11];
    const float* a_dst2      = (const float*)d_in[12];
    const float* b2          = (const float*)d_in[13];
    const float* Wc1         = (const float*)d_in[14];
    const float* bc1         = (const float*)d_in[15];
    const float* Wc2         = (const float*)d_in[16];
    const float* bc2         = (const float*)d_in[17];
    const float* W2          = (const float*)d_in[10];
    float* out = (float*)d_out;

    cudaFuncSetAttribute(gemm1_gat1_kernel, cudaFuncAttributeMaxDynamicSharedMemorySize, KA_SMEM);
    cudaFuncSetAttribute(gemm2_rest_kernel, cudaFuncAttributeMaxDynamicSharedMemorySize, KB_SMEM);

    float* gate_out = (out_size >= 64) ? (out + (out_size - 64)) : nullptr;

    // 1) weight prep + gate
    prep_weights_kernel<<<323, 256>>>(W_align, W1, W2, b_align, gate_logits, gate_out);

    // 2) per-(graph, head): GEMM1 + GAT1 -> o1 (bf16 hi/lo)
    gemm1_gat1_kernel<<<dim3(HEADS, B_GRAPHS), 128, KA_SMEM>>>(
        emb, edge_index, gate_logits, a_src1, a_dst1, b1);

    // 3) per-graph: GEMM2 + GAT2 + pool + classifier
    gemm2_rest_kernel<<<B_GRAPHS, 256, KB_SMEM>>>(
        edge_index, a_src2, a_dst2, b2, Wc1, bc1, Wc2, bc2, out);
}

// round 6
// speedup vs baseline: 1.7575x; 1.0438x over previous
#include <cuda_runtime.h>
#include <cuda_bf16.h>
#include <math.h>
#include <cstdint>

// ---------------- problem constants ----------------
#define B_GRAPHS 2048
#define F_NODES  64
#define D_IN     32
#define HDIM     128
#define HEADS    4
#define NC       16
#define EPG      128
#define N_NODES  (B_GRAPHS * F_NODES)        // 131072
#define E_EDGES  (B_GRAPHS * EPG)            // 262144

// ---------------- device-global scratch ----------------
// W1' = Wa@W1 in B-fragment layout: [ks(2)][gnt(64)][lane(32)] -> uint2 (b0,b1)
__device__ uint2 g_w1pk_h[2 * 64 * 32];
__device__ uint2 g_w1pk_l[2 * 64 * 32];
__device__ float g_c1[512];                   // b_align @ W1
// W2^T in B-fragment layout: [ks(32)][gnt(16)][lane(32)] -> uint2
__device__ uint2 g_w2pk_h[32 * 16 * 32];
__device__ uint2 g_w2pk_l[32 * 16 * 32];
__device__ __nv_bfloat16 g_o1h[(size_t)N_NODES * 512];
__device__ __nv_bfloat16 g_o1l[(size_t)N_NODES * 512];

// ---------------- PTX helpers (sm_80+; no tcgen05 — ptxas targets compute_103) ----------------
__device__ __forceinline__ uint32_t smem_to_u32(const void* p) {
    uint32_t a;
    asm("{ .reg .u64 tmp; cvta.to.shared.u64 tmp, %1; cvt.u32.u64 %0, tmp; }" : "=r"(a) : "l"(p));
    return a;
}
__device__ __forceinline__ void cp16(uint32_t saddr, const void* g) {
    asm volatile("cp.async.cg.shared.global [%0], [%1], 16;"
                 :: "r"(saddr), "l"(g) : "memory");
}
#define CP_COMMIT() asm volatile("cp.async.commit_group;" ::: "memory")
#define CP_WAIT0()  asm volatile("cp.async.wait_group 0;" ::: "memory")
#define CP_WAIT1()  asm volatile("cp.async.wait_group 1;" ::: "memory")

#define LDSM_X4(r0, r1, r2, r3, addr) \
    asm volatile("ldmatrix.sync.aligned.m8n8.x4.shared.b16 {%0,%1,%2,%3}, [%4];" \
                 : "=r"(r0), "=r"(r1), "=r"(r2), "=r"(r3) : "r"(addr))

#define MMA16816(d, a, b0, b1) \
    asm volatile("mma.sync.aligned.m16n8k16.row.col.f32.bf16.bf16.f32 " \
                 "{%0,%1,%2,%3}, {%4,%5,%6,%7}, {%8,%9}, {%0,%1,%2,%3};" \
                 : "+f"((d)[0]), "+f"((d)[1]), "+f"((d)[2]), "+f"((d)[3]) \
                 : "r"((a)[0]), "r"((a)[1]), "r"((a)[2]), "r"((a)[3]), "r"(b0), "r"(b1))

__device__ __forceinline__ void atomicMaxFloatS(float* addr, float val) {
    int* ai = (int*)addr;
    int old = *ai;
    while (__int_as_float(old) < val) {
        int assumed = old;
        old = atomicCAS(ai, assumed, __float_as_int(val));
        if (old == assumed) break;
    }
}
__device__ __forceinline__ uint32_t pack_bf16x2(float a, float b) {
    __nv_bfloat162 v(__float2bfloat16(a), __float2bfloat16(b));
    return *(uint32_t*)&v;
}

// ---------------- prep: weights -> B-fragment layout, + c1 + gate ----------------
// B-fragment element map (validated via ldmatrix path in prior rounds):
//   b0 half0: B[k = ks*16 + reg*8 + (lane&3)*2    ][n = gnt*8 + (lane>>2)]
//   b0 half1: same with k+1;  reg 0 -> .x, reg 1 -> .y of uint2
__global__ __launch_bounds__(256) void prep_weights_kernel(
    const float* __restrict__ Wa, const float* __restrict__ W1,
    const float* __restrict__ W2, const float* __restrict__ b_align,
    const float* __restrict__ gl, float* __restrict__ gate_out)
{
    int gid = blockIdx.x * 256 + threadIdx.x;
    if (gid < 8192) {
        // w1pk: wid -> (reg, lane, gnt(64), ks(2)); value = (Wa@W1)[k][n]
        int wid = gid;
        int reg = wid & 1, lane = (wid >> 1) & 31, gnt = (wid >> 6) & 63, ks = wid >> 12;
        int n = gnt * 8 + (lane >> 2);
        int k = ks * 16 + reg * 8 + (lane & 3) * 2;
        float v0 = 0.f, v1 = 0.f;
#pragma unroll 8
        for (int m = 0; m < 128; m++) {
            v0 = fmaf(Wa[k * 128 + m], W1[m * 512 + n], v0);
            v1 = fmaf(Wa[(k + 1) * 128 + m], W1[m * 512 + n], v1);
        }
        float h0 = __bfloat162float(__float2bfloat16(v0));
        float h1 = __bfloat162float(__float2bfloat16(v1));
        ((uint32_t*)g_w1pk_h)[wid] = pack_bf16x2(v0, v1);
        ((uint32_t*)g_w1pk_l)[wid] = pack_bf16x2(v0 - h0, v1 - h1);
    } else if (gid < 40960) {
        // w2pk: value = W2[k][n] (W2: [512][128] row-major)
        int wid = gid - 8192;
        int reg = wid & 1, lane = (wid >> 1) & 31, gnt = (wid >> 6) & 15, ks = wid >> 10;
        int n = gnt * 8 + (lane >> 2);
        int k = ks * 16 + reg * 8 + (lane & 3) * 2;
        float v0 = W2[k * 128 + n];
        float v1 = W2[(k + 1) * 128 + n];
        float h0 = __bfloat162float(__float2bfloat16(v0));
        float h1 = __bfloat162float(__float2bfloat16(v1));
        ((uint32_t*)g_w2pk_h)[wid] = pack_bf16x2(v0, v1);
        ((uint32_t*)g_w2pk_l)[wid] = pack_bf16x2(v0 - h0, v1 - h1);
    } else if (gid < 41472) {
        int n = gid - 40960;
        float acc = 0.f;
#pragma unroll 8
        for (int m = 0; m < 128; m++) acc = fmaf(b_align[m], W1[m * 512 + n], acc);
        g_c1[n] = acc;
    } else if (gid < 41536) {
        int f = gid - 41472;
        if (gate_out != nullptr) gate_out[f] = 1.0f / (1.0f + expf(-gl[f]));
    }
}

// ---------------- kernel A: per (graph, head) — GEMM1 + GAT1 ----------------
// smem dyn: [0,10240) emb hi/lo (80B rows) | [10240,44032) h1 fp32 64x132
#define KA_SMEM 44032

__global__ __launch_bounds__(128, 4) void gemm1_gat1_kernel(
    const float* __restrict__ emb, const int* __restrict__ eidx,
    const float* __restrict__ gl,
    const float* __restrict__ a_src1, const float* __restrict__ a_dst1,
    const float* __restrict__ b1)
{
    extern __shared__ __align__(16) char smem[];
    __nv_bfloat16* s_embh = (__nv_bfloat16*)smem;
    __nv_bfloat16* s_embl = (__nv_bfloat16*)(smem + 5120);
    float* s_h1 = (float*)(smem + 10240);        // stride 132 fp32
    uint32_t sb = smem_to_u32(smem);

    __shared__ float s_gate[64], s_ssrc[64], s_sdst[64], s_smax[64], s_ssum[64], s_c1[128];
    __shared__ float s_eprob[192];
    __shared__ int   s_eS[192], s_eT[192], s_order[192], s_startc[65], s_deg[64], s_cur[64];

    int h = blockIdx.x, b = blockIdx.y;
    int hoff = h * 128;
    int t = threadIdx.x, lane = t & 31, w = t >> 5;
    int node0 = b * 64;

    if (t < 64) {
        s_deg[t] = 0; s_cur[t] = 0;
        s_gate[t] = 1.0f / (1.0f + expf(-gl[t]));
        s_smax[t] = -1e30f; s_ssum[t] = 0.f;
    }
    s_c1[t] = g_c1[hoff + t];
    s_eS[t] = eidx[b * 128 + t] - node0;
    s_eT[t] = eidx[E_EDGES + b * 128 + t] - node0;
    if (t < 64) { s_eS[128 + t] = t; s_eT[128 + t] = t; }
    // emb -> hi/lo bf16 smem (80B rows)
#pragma unroll
    for (int i = 0; i < 4; i++) {
        int f = t + i * 128;                     // 512 float4
        int row = f >> 3, p = f & 7;
        float4 v = *(const float4*)(emb + (size_t)(node0 + row) * 32 + p * 4);
        __nv_bfloat16* ph = s_embh + row * 40 + p * 4;
        __nv_bfloat16* pl = s_embl + row * 40 + p * 4;
        __nv_bfloat16 h0 = __float2bfloat16(v.x), h1v = __float2bfloat16(v.y);
        __nv_bfloat16 h2 = __float2bfloat16(v.z), h3 = __float2bfloat16(v.w);
        ph[0] = h0; ph[1] = h1v; ph[2] = h2; ph[3] = h3;
        pl[0] = __float2bfloat16(v.x - __bfloat162float(h0));
        pl[1] = __float2bfloat16(v.y - __bfloat162float(h1v));
        pl[2] = __float2bfloat16(v.z - __bfloat162float(h2));
        pl[3] = __float2bfloat16(v.w - __bfloat162float(h3));
    }
    __syncthreads();
    for (int e = t; e < 192; e += 128) atomicAdd(&s_deg[s_eT[e]], 1);
    __syncthreads();
    if (t == 0) {
        int a = 0;
        for (int i = 0; i < 64; i++) { s_startc[i] = a; a += s_deg[i]; }
        s_startc[64] = a;
    }
    __syncthreads();
    for (int e = t; e < 192; e += 128) {
        int tt = s_eT[e];
        int pos = atomicAdd(&s_cur[tt], 1);
        s_order[s_startc[tt] + pos] = e;
    }
    __syncthreads();

    // ---- GEMM1: warp w = rows w*16..+15, all 128 head cols; K=32, 3-pass hi/lo ----
    float acc[16][4];
#pragma unroll
    for (int i = 0; i < 16; i++)
#pragma unroll
        for (int r = 0; r < 4; r++) acc[i][r] = 0.f;

    uint32_t aH = sb + (uint32_t)((w * 16 + (lane & 15)) * 80 + (lane >> 4) * 16);
    uint32_t aL = aH + 5120;

#pragma unroll
    for (int kk = 0; kk < 2; kk++) {
        uint32_t ah[4], al[4];
        LDSM_X4(ah[0], ah[1], ah[2], ah[3], aH + kk * 32);
        LDSM_X4(al[0], al[1], al[2], al[3], aL + kk * 32);
        int base = (kk * 64 + h * 16) * 32 + lane;
#pragma unroll
        for (int i = 0; i < 16; i++) {
            uint2 bh = __ldg(&g_w1pk_h[base + i * 32]);
            uint2 bl = __ldg(&g_w1pk_l[base + i * 32]);
            MMA16816(acc[i], ah, bh.x, bh.y);
            MMA16816(acc[i], ah, bl.x, bl.y);
            MMA16816(acc[i], al, bh.x, bh.y);
        }
    }

    // epilogue: h1 = gate * (acc + c1)
    int gr = lane >> 2, gc = (lane & 3) * 2;
    int r0 = w * 16 + gr;
    float g0 = s_gate[r0], g1 = s_gate[r0 + 8];
#pragma unroll
    for (int i = 0; i < 16; i++) {
        int col = i * 8 + gc;
        s_h1[r0 * 132 + col]           = g0 * (acc[i][0] + s_c1[col]);
        s_h1[r0 * 132 + col + 1]       = g0 * (acc[i][1] + s_c1[col + 1]);
        s_h1[(r0 + 8) * 132 + col]     = g1 * (acc[i][2] + s_c1[col]);
        s_h1[(r0 + 8) * 132 + col + 1] = g1 * (acc[i][3] + s_c1[col + 1]);
    }
    __syncthreads();

    // ---- GAT1 on this head ----
    {
        float a0 = __ldg(&a_src1[hoff + lane * 4]);
        float a1 = __ldg(&a_src1[hoff + lane * 4 + 1]);
        float a2 = __ldg(&a_src1[hoff + lane * 4 + 2]);
        float a3 = __ldg(&a_src1[hoff + lane * 4 + 3]);
        float d0 = __ldg(&a_dst1[hoff + lane * 4]);
        float d1 = __ldg(&a_dst1[hoff + lane * 4 + 1]);
        float d2 = __ldg(&a_dst1[hoff + lane * 4 + 2]);
        float d3 = __ldg(&a_dst1[hoff + lane * 4 + 3]);
#pragma unroll
        for (int i = w; i < 64; i += 4) {
            float4 hv = *(const float4*)(s_h1 + i * 132 + lane * 4);
            float s1 = hv.x * a0 + hv.y * a1 + hv.z * a2 + hv.w * a3;
            float s2 = hv.x * d0 + hv.y * d1 + hv.z * d2 + hv.w * d3;
#pragma unroll
            for (int off = 16; off > 0; off >>= 1) {
                s1 += __shfl_xor_sync(0xffffffffu, s1, off);
                s2 += __shfl_xor_sync(0xffffffffu, s2, off);
            }
            if (lane == 0) { s_ssrc[i] = s1; s_sdst[i] = s2; }
        }
    }
    __syncthreads();
    for (int e = t; e < 192; e += 128) {
        float sc = s_ssrc[s_eS[e]] + s_sdst[s_eT[e]];
        sc = sc > 0.f ? sc : 0.2f * sc;
        s_eprob[e] = sc;
        atomicMaxFloatS(&s_smax[s_eT[e]], sc);
    }
    __syncthreads();
    for (int e = t; e < 192; e += 128) {
        float p = expf(s_eprob[e] - s_smax[s_eT[e]]);
        s_eprob[e] = p;
        atomicAdd(&s_ssum[s_eT[e]], p);
    }
    __syncthreads();
    // aggregate + bias + elu -> o1 (bf16 hi/lo) global
    {
        int d = t;
        float bd = __ldg(&b1[hoff + d]);
        for (int tt = 0; tt < 64; tt++) {
            float a = 0.f;
            int s0 = s_startc[tt], s1 = s_startc[tt + 1];
            for (int k = s0; k < s1; k++) {
                int e = s_order[k];
                a = fmaf(s_eprob[e], s_h1[s_eS[e] * 132 + d], a);
            }
            float val = a / (s_ssum[tt] + 1e-16f) + bd;
            val = val > 0.f ? val : (expf(val) - 1.f);
            __nv_bfloat16 hi = __float2bfloat16(val);
            size_t o = (size_t)(node0 + tt) * 512 + hoff + d;
            g_o1h[o] = hi;
            g_o1l[o] = __float2bfloat16(val - __bfloat162float(hi));
        }
    }
}

// ---------------- kernel B: per graph — GEMM2 + GAT2 + pool + classifier ----------------
// smem dyn: [0,33792) h2 fp32 64x132 | [33792,103424) o1 chunk buffers 2 x 34816
//   buffer: o1h 64x272 (17408) | o1l 64x272; after GEMM: o2 fp32 64x128 overlays
#define KB_BUF   34816
#define KB_ARR   17408
#define KB_SMEM  103424

__global__ __launch_bounds__(256, 2) void gemm2_rest_kernel(
    const int* __restrict__ eidx,
    const float* __restrict__ a_src2, const float* __restrict__ a_dst2,
    const float* __restrict__ b2,
    const float* __restrict__ Wc1, const float* __restrict__ bc1,
    const float* __restrict__ Wc2, const float* __restrict__ bc2,
    float* __restrict__ outp)
{
    extern __shared__ __align__(16) char smem[];
    float* s_h2 = (float*)smem;                   // stride 132
    char*  s_buf = smem + 33792;
    float* s_o2 = (float*)(smem + 33792);         // stride 128, after GEMM
    uint32_t sbBuf = smem_to_u32(s_buf);

    __shared__ float s_ssrc[64], s_sdst[64], s_smax[64], s_ssum[64];
    __shared__ float s_eprob[192];
    __shared__ int   s_eS[192], s_eT[192], s_order[192], s_startc[65], s_deg[64], s_cur[64];
    __shared__ float s_g[128], s_hc[64];

    int b = blockIdx.x, t = threadIdx.x, lane = t & 31, w = t >> 5;
    int wm = w >> 1, wn = w & 1;
    int node0 = b * 64;

    // chunk = k128: 2048 cp16 pieces (o1 hi + lo)
    auto loadChunk = [&](int kc) {
        uint32_t dst = sbBuf + (uint32_t)(kc & 1) * KB_BUF;
#pragma unroll
        for (int i = 0; i < 8; i++) {
            int item = t + i * 256;
            int arr = item >> 10;                 // 0 hi, 1 lo
            int r = (item & 1023) >> 4;
            int p = item & 15;
            const __nv_bfloat16* src =
                (arr ? g_o1l : g_o1h) + (size_t)(node0 + r) * 512 + kc * 128 + p * 8;
            cp16(dst + arr * KB_ARR + r * 272 + p * 16, src);
        }
    };

    loadChunk(0); CP_COMMIT();

    // CSR / init (overlaps chunk-0 load)
    if (t < 64) {
        s_deg[t] = 0; s_cur[t] = 0;
        s_smax[t] = -1e30f; s_ssum[t] = 0.f;
    }
    if (t < 192) {
        int s, tt;
        if (t < 128) { s = eidx[b * 128 + t] - node0; tt = eidx[E_EDGES + b * 128 + t] - node0; }
        else         { s = t - 128; tt = s; }
        s_eS[t] = s; s_eT[t] = tt;
    }
    __syncthreads();
    if (t < 192) atomicAdd(&s_deg[s_eT[t]], 1);
    __syncthreads();
    if (t == 0) {
        int a = 0;
        for (int i = 0; i < 64; i++) { s_startc[i] = a; a += s_deg[i]; }
        s_startc[64] = a;
    }
    __syncthreads();
    if (t < 192) {
        int tt = s_eT[t];
        int pos = atomicAdd(&s_cur[tt], 1);
        s_order[s_startc[tt] + pos] = t;
    }

    // ---- GEMM2: h2 = o1 @ w2t^T, K=512 in 4 chunks of k128; 3-pass hi/lo ----
    float acc[8][4];
#pragma unroll
    for (int i = 0; i < 8; i++)
#pragma unroll
        for (int r = 0; r < 4; r++) acc[i][r] = 0.f;

    uint32_t aoff = (uint32_t)((wm * 16 + (lane & 15)) * 272 + (lane >> 4) * 16);

    for (int kc = 0; kc < 4; kc++) {
        if (kc + 1 < 4) { loadChunk(kc + 1); CP_COMMIT(); CP_WAIT1(); }
        else            { CP_WAIT0(); }
        __syncthreads();

        uint32_t bufb = sbBuf + (uint32_t)(kc & 1) * KB_BUF;
#pragma unroll
        for (int kk = 0; kk < 8; kk++) {
            uint32_t ah[4], al[4];
            LDSM_X4(ah[0], ah[1], ah[2], ah[3], bufb + aoff + kk * 32);
            LDSM_X4(al[0], al[1], al[2], al[3], bufb + KB_ARR + aoff + kk * 32);
            int gks = kc * 8 + kk;
            int base = (gks * 16 + wn * 8) * 32 + lane;
#pragma unroll
            for (int i = 0; i < 8; i++) {
                uint2 bh = __ldg(&g_w2pk_h[base + i * 32]);
                uint2 bl = __ldg(&g_w2pk_l[base + i * 32]);
                MMA16816(acc[i], ah, bh.x, bh.y);
                MMA16816(acc[i], ah, bl.x, bl.y);
                MMA16816(acc[i], al, bh.x, bh.y);
            }
        }
        __syncthreads();
    }

    // write h2
    int gr = lane >> 2, gc = (lane & 3) * 2;
    int r0 = wm * 16 + gr;
#pragma unroll
    for (int i = 0; i < 8; i++) {
        int col = wn * 64 + i * 8 + gc;
        s_h2[r0 * 132 + col]           = acc[i][0];
        s_h2[r0 * 132 + col + 1]       = acc[i][1];
        s_h2[(r0 + 8) * 132 + col]     = acc[i][2];
        s_h2[(r0 + 8) * 132 + col + 1] = acc[i][3];
    }
    __syncthreads();

    // ---- GAT2 (1 head) ----
    {
        float a0 = __ldg(&a_src2[lane * 4]);
        float a1 = __ldg(&a_src2[lane * 4 + 1]);
        float a2 = __ldg(&a_src2[lane * 4 + 2]);
        float a3 = __ldg(&a_src2[lane * 4 + 3]);
        float d0 = __ldg(&a_dst2[lane * 4]);
        float d1 = __ldg(&a_dst2[lane * 4 + 1]);
        float d2 = __ldg(&a_dst2[lane * 4 + 2]);
        float d3 = __ldg(&a_dst2[lane * 4 + 3]);
#pragma unroll
        for (int i = w; i < 64; i += 8) {
            float4 hv = *(const float4*)(s_h2 + i * 132 + lane * 4);
            float s1 = hv.x * a0 + hv.y * a1 + hv.z * a2 + hv.w * a3;
            float s2 = hv.x * d0 + hv.y * d1 + hv.z * d2 + hv.w * d3;
#pragma unroll
            for (int off = 16; off > 0; off >>= 1) {
                s1 += __shfl_xor_sync(0xffffffffu, s1, off);
                s2 += __shfl_xor_sync(0xffffffffu, s2, off);
            }
            if (lane == 0) { s_ssrc[i] = s1; s_sdst[i] = s2; }
        }
    }
    __syncthreads();
    if (t < 192) {
        float sc = s_ssrc[s_eS[t]] + s_sdst[s_eT[t]];
        sc = sc > 0.f ? sc : 0.2f * sc;
        s_eprob[t] = sc;
        atomicMaxFloatS(&s_smax[s_eT[t]], sc);
    }
    __syncthreads();
    if (t < 192) {
        float p = expf(s_eprob[t] - s_smax[s_eT[t]]);
        s_eprob[t] = p;
        atomicAdd(&s_ssum[s_eT[t]], p);
    }
    __syncthreads();
    {
        int d = t & 127, half = t >> 7;
        float bd = __ldg(&b2[d]);
        for (int tt = half * 32; tt < half * 32 + 32; tt++) {
            float a = 0.f;
            int s0 = s_startc[tt], s1 = s_startc[tt + 1];
            for (int k = s0; k < s1; k++) {
                int e = s_order[k];
                a = fmaf(s_eprob[e], s_h2[s_eS[e] * 132 + d], a);
            }
            s_o2[tt * 128 + d] = a / (s_ssum[tt] + 1e-16f) + bd;
        }
    }
    __syncthreads();

    // ---- mean pool + classifier ----
    if (t < 128) {
        float a = 0.f;
#pragma unroll 8
        for (int i = 0; i < 64; i++) a += s_o2[i * 128 + t];
        s_g[t] = a * (1.0f / 64.0f);
    }
    __syncthreads();
    if (t < 64) {
        float a = __ldg(&bc1[t]);
#pragma unroll 8
        for (int d = 0; d < 128; d++) a = fmaf(s_g[d], __ldg(&Wc1[d * 64 + t]), a);
        s_hc[t] = a > 0.f ? a : 0.01f * a;
    }
    __syncthreads();
    if (t < 16) {
        float a = __ldg(&bc2[t]);
#pragma unroll 8
        for (int j = 0; j < 64; j++) a = fmaf(s_hc[j], __ldg(&Wc2[j * 16 + t]), a);
        outp[(size_t)b * 16 + t] = a;
    }
}

// ---------------- launch ----------------
extern "C" void kernel_launch(void* const* d_in, const int* in_sizes, int n_in,
                              void* d_out, int out_size)
{
    const float* emb         = (const float*)d_in[0];
    const int*   edge_index  = (const int*)d_in[1];
    const float* W_align     = (const float*)d_in[3];
    const float* b_align     = (const float*)d_in[4];
    const float* gate_logits = (const float*)d_in[5];
    const float* W1          = (const float*)d_in[6];
    const float* a_src1      = (const float*)d_in[7];
    const float* a_dst1      = (const float*)d_in[8];
    const float* b1          = (const float*)d_in[9];
    const float* W2          = (const float*)d_in[10];
    const float* a_src2      = (const float*)d_in[11];
    const float* a_dst2      = (const float*)d_in[12];
    const float* b2          = (const float*)d_in[13];
    const float* Wc1         = (const float*)d_in[14];
    const float* bc1         = (const float*)d_in[15];
    const float* Wc2         = (const float*)d_in[16];
    const float* bc2         = (const float*)d_in[17];
    float* out = (float*)d_out;

    cudaFuncSetAttribute(gemm1_gat1_kernel, cudaFuncAttributeMaxDynamicSharedMemorySize, KA_SMEM);
    cudaFuncSetAttribute(gemm2_rest_kernel, cudaFuncAttributeMaxDynamicSharedMemorySize, KB_SMEM);

    float* gate_out = (out_size >= 64) ? (out + (out_size - 64)) : nullptr;

    // 1) weight prep (fragment packing) + gate
    prep_weights_kernel<<<163, 256>>>(W_align, W1, W2, b_align, gate_logits, gate_out);

    // 2) per-(graph, head): GEMM1 + GAT1 -> o1 (bf16 hi/lo)
    gemm1_gat1_kernel<<<dim3(HEADS, B_GRAPHS), 128, KA_SMEM>>>(
        emb, edge_index, gate_logits, a_src1, a_dst1, b1);

    // 3) per-graph: GEMM2 + GAT2 + pool + classifier
    gemm2_rest_kernel<<<B_GRAPHS, 256, KB_SMEM>>>(
        edge_index, a_src2, a_dst2, b2, Wc1, bc1, Wc2, bc2, out);
}

// round 7
// speedup vs baseline: 2.0286x; 1.1542x over previous
#include <cuda_runtime.h>
#include <cuda_bf16.h>
#include <math.h>
#include <cstdint>

// ---------------- problem constants ----------------
#define B_GRAPHS 2048
#define F_NODES  64
#define D_IN     32
#define HDIM     128
#define HEADS    4
#define NC       16
#define EPG      128
#define N_NODES  (B_GRAPHS * F_NODES)        // 131072
#define E_EDGES  (B_GRAPHS * EPG)            // 262144

// ---------------- device-global scratch ----------------
// W1' = Wa@W1 in B-fragment layout: [ks(2)][gnt(64)][lane(32)] -> uint2
__device__ uint2 g_w1pk_h[2 * 64 * 32];
__device__ uint2 g_w1pk_l[2 * 64 * 32];
__device__ float g_c1[512];                   // b_align @ W1
// W2^T in B-fragment layout: [ks(32)][gnt(16)][lane(32)] -> uint2
__device__ uint2 g_w2pk_h[32 * 16 * 32];
__device__ uint2 g_w2pk_l[32 * 16 * 32];
// emb in A-fragment layout: [rowgrp(8192)][ks(2)][lane(32)] -> uint4 (a0..a3)
__device__ uint4 g_embA_h[(size_t)8192 * 2 * 32];
__device__ uint4 g_embA_l[(size_t)8192 * 2 * 32];

// ---------------- PTX helpers (sm_80+; no tcgen05 — ptxas targets compute_103) ----------------
__device__ __forceinline__ uint32_t smem_to_u32(const void* p) {
    uint32_t a;
    asm("{ .reg .u64 tmp; cvta.to.shared.u64 tmp, %1; cvt.u32.u64 %0, tmp; }" : "=r"(a) : "l"(p));
    return a;
}
#define LDSM_X4(r0, r1, r2, r3, addr) \
    asm volatile("ldmatrix.sync.aligned.m8n8.x4.shared.b16 {%0,%1,%2,%3}, [%4];" \
                 : "=r"(r0), "=r"(r1), "=r"(r2), "=r"(r3) : "r"(addr))

#define MMA16816(d, a, b0, b1) \
    asm volatile("mma.sync.aligned.m16n8k16.row.col.f32.bf16.bf16.f32 " \
                 "{%0,%1,%2,%3}, {%4,%5,%6,%7}, {%8,%9}, {%0,%1,%2,%3};" \
                 : "+f"((d)[0]), "+f"((d)[1]), "+f"((d)[2]), "+f"((d)[3]) \
                 : "r"((a)[0]), "r"((a)[1]), "r"((a)[2]), "r"((a)[3]), "r"(b0), "r"(b1))

__device__ __forceinline__ void atomicMaxFloatS(float* addr, float val) {
    int* ai = (int*)addr;
    int old = *ai;
    while (__int_as_float(old) < val) {
        int assumed = old;
        old = atomicCAS(ai, assumed, __float_as_int(val));
        if (old == assumed) break;
    }
}
__device__ __forceinline__ uint32_t pack_bf16x2(float a, float b) {
    __nv_bfloat162 v(__float2bfloat16(a), __float2bfloat16(b));
    return *(uint32_t*)&v;
}
__device__ __forceinline__ void split_pair(float a, float b, uint32_t& hi, uint32_t& lo) {
    __nv_bfloat16 ha = __float2bfloat16(a), hb = __float2bfloat16(b);
    __nv_bfloat162 H(ha, hb);
    __nv_bfloat162 L(__float2bfloat16(a - __bfloat162float(ha)),
                     __float2bfloat16(b - __bfloat162float(hb)));
    hi = *(uint32_t*)&H;
    lo = *(uint32_t*)&L;
}

// ---------------- prep 1: weights -> B-fragment layout, + c1 + gate ----------------
__global__ __launch_bounds__(256) void prep_weights_kernel(
    const float* __restrict__ Wa, const float* __restrict__ W1,
    const float* __restrict__ W2, const float* __restrict__ b_align,
    const float* __restrict__ gl, float* __restrict__ gate_out)
{
    int gid = blockIdx.x * 256 + threadIdx.x;
    if (gid < 8192) {
        int wid = gid;
        int reg = wid & 1, lane = (wid >> 1) & 31, gnt = (wid >> 6) & 63, ks = wid >> 12;
        int n = gnt * 8 + (lane >> 2);
        int k = ks * 16 + reg * 8 + (lane & 3) * 2;
        float v0 = 0.f, v1 = 0.f;
#pragma unroll 8
        for (int m = 0; m < 128; m++) {
            v0 = fmaf(Wa[k * 128 + m], W1[m * 512 + n], v0);
            v1 = fmaf(Wa[(k + 1) * 128 + m], W1[m * 512 + n], v1);
        }
        uint32_t hi, lo;
        split_pair(v0, v1, hi, lo);
        ((uint32_t*)g_w1pk_h)[wid] = hi;
        ((uint32_t*)g_w1pk_l)[wid] = lo;
    } else if (gid < 40960) {
        int wid = gid - 8192;
        int reg = wid & 1, lane = (wid >> 1) & 31, gnt = (wid >> 6) & 15, ks = wid >> 10;
        int n = gnt * 8 + (lane >> 2);
        int k = ks * 16 + reg * 8 + (lane & 3) * 2;
        uint32_t hi, lo;
        split_pair(W2[k * 128 + n], W2[(k + 1) * 128 + n], hi, lo);
        ((uint32_t*)g_w2pk_h)[wid] = hi;
        ((uint32_t*)g_w2pk_l)[wid] = lo;
    } else if (gid < 41472) {
        int n = gid - 40960;
        float acc = 0.f;
#pragma unroll 8
        for (int m = 0; m < 128; m++) acc = fmaf(b_align[m], W1[m * 512 + n], acc);
        g_c1[n] = acc;
    } else if (gid < 41536) {
        int f = gid - 41472;
        if (gate_out != nullptr) gate_out[f] = 1.0f / (1.0f + expf(-gl[f]));
    }
}

// ---------------- prep 2: emb -> A-fragment layout (hi/lo) ----------------
__global__ __launch_bounds__(256) void prep_emb_kernel(const float* __restrict__ emb)
{
    int gid = blockIdx.x * 256 + threadIdx.x;    // 524288
    int lane = gid & 31;
    int ks = (gid >> 5) & 1;
    int grp = gid >> 6;                          // 0..8191 (16-row groups)
    int gr = lane >> 2, gc = (lane & 3) * 2;
    const float* base = emb + (size_t)grp * 16 * 32 + ks * 16;

    float v0 = base[gr * 32 + gc],           v1 = base[gr * 32 + gc + 1];
    float v2 = base[(gr + 8) * 32 + gc],     v3 = base[(gr + 8) * 32 + gc + 1];
    float v4 = base[gr * 32 + gc + 8],       v5 = base[gr * 32 + gc + 9];
    float v6 = base[(gr + 8) * 32 + gc + 8], v7 = base[(gr + 8) * 32 + gc + 9];

    uint4 H, L;
    split_pair(v0, v1, H.x, L.x);
    split_pair(v2, v3, H.y, L.y);
    split_pair(v4, v5, H.z, L.z);
    split_pair(v6, v7, H.w, L.w);
    g_embA_h[gid] = H;
    g_embA_l[gid] = L;
}

// ---------------- mega kernel: one CTA per graph, o1 never leaves SMEM ----------------
// dynamic smem: [0,33792) h1/h2 fp32 64x132 | [33792,51200) o1h bf16 64x136 |
//               [51200,68608) o1l bf16 64x136 ;  o2 fp32 64x128 overlays o1 region
#define MG_O1H 33792
#define MG_O1L 51200
#define MG_DYN 68608

__global__ __launch_bounds__(256, 2) void mega_kernel(
    const int* __restrict__ eidx, const float* __restrict__ gl,
    const float* __restrict__ a_src1, const float* __restrict__ a_dst1,
    const float* __restrict__ b1,
    const float* __restrict__ a_src2, const float* __restrict__ a_dst2,
    const float* __restrict__ b2,
    const float* __restrict__ Wc1, const float* __restrict__ bc1,
    const float* __restrict__ Wc2, const float* __restrict__ bc2,
    float* __restrict__ outp)
{
    extern __shared__ __align__(16) char smem[];
    float* s_h1 = (float*)smem;                               // stride 132
    __nv_bfloat16* s_o1h = (__nv_bfloat16*)(smem + MG_O1H);   // stride 136
    __nv_bfloat16* s_o1l = (__nv_bfloat16*)(smem + MG_O1L);
    float* s_o2 = (float*)(smem + MG_O1H);                    // stride 128 (after GEMMs)
    uint32_t sbO1h = smem_to_u32(smem) + MG_O1H;
    uint32_t sbO1l = smem_to_u32(smem) + MG_O1L;

    __shared__ int   s_ed[192], s_slot[192], s_osrc[192], s_startc[65], s_deg[64], s_cur[64];
    __shared__ float s_eprob[192], s_aprob[192];
    __shared__ float s_ssrc[64], s_sdst[64], s_smax[64], s_ssum[64];
    __shared__ float s_gv[128], s_hc[64];

    int b = blockIdx.x, t = threadIdx.x, lane = t & 31, w = t >> 5;
    int wm = w >> 1, wn = w & 1;
    int gr = lane >> 2, gc = (lane & 3) * 2;
    int node0 = b * 64;
    int r0 = wm * 16 + gr;

    // ---------- phase 0 ----------
    if (t < 64) { s_deg[t] = 0; s_cur[t] = 0; }
    if (t < 192) {
        int src, tt;
        if (t < 128) { src = eidx[b * 128 + t] - node0; tt = eidx[E_EDGES + b * 128 + t] - node0; }
        else         { src = t - 128; tt = src; }
        s_ed[t] = src | (tt << 8);
    }
    // preload A-frags (same for every head)
    int grp = b * 4 + wm;
    uint4 eh4[2], el4[2];
    eh4[0] = __ldg(&g_embA_h[(size_t)(grp * 2 + 0) * 32 + lane]);
    eh4[1] = __ldg(&g_embA_h[(size_t)(grp * 2 + 1) * 32 + lane]);
    el4[0] = __ldg(&g_embA_l[(size_t)(grp * 2 + 0) * 32 + lane]);
    el4[1] = __ldg(&g_embA_l[(size_t)(grp * 2 + 1) * 32 + lane]);
    float gate0 = 1.0f / (1.0f + __expf(-__ldg(&gl[r0])));
    float gate1 = 1.0f / (1.0f + __expf(-__ldg(&gl[r0 + 8])));

    __syncthreads();
    if (t < 192) atomicAdd(&s_deg[s_ed[t] >> 8], 1);
    __syncthreads();
    if (w == 0) {                                    // warp scan prefix (64 entries, 2/lane)
        int v0 = s_deg[lane * 2], v1 = s_deg[lane * 2 + 1];
        int p = v0 + v1, run = p;
#pragma unroll
        for (int off = 1; off < 32; off <<= 1) {
            int n = __shfl_up_sync(0xffffffffu, run, off);
            if (lane >= off) run += n;
        }
        s_startc[lane * 2] = run - p;
        s_startc[lane * 2 + 1] = run - p + v0;
        if (lane == 31) s_startc[64] = run;
    }
    __syncthreads();
    if (t < 192) {
        int tt = s_ed[t] >> 8, src = s_ed[t] & 255;
        int pos = atomicAdd(&s_cur[tt], 1);
        int slot = s_startc[tt] + pos;
        s_slot[t] = slot;
        s_osrc[slot] = src * 132;                    // premultiplied row stride
    }

    float acc2[8][4] = {};                           // persistent GEMM2 accumulator

    // ---------- head loop: GEMM1 -> GAT1 -> GEMM2 partial ----------
    for (int h = 0; h < HEADS; h++) {
        int hoff = h * 128;

        float acc1[8][4] = {};
#pragma unroll
        for (int ks = 0; ks < 2; ks++) {
            uint32_t Ah[4] = { eh4[ks].x, eh4[ks].y, eh4[ks].z, eh4[ks].w };
            uint32_t Al[4] = { el4[ks].x, el4[ks].y, el4[ks].z, el4[ks].w };
            int base = (ks * 64 + h * 16 + wn * 8) * 32 + lane;
#pragma unroll
            for (int i = 0; i < 8; i++) {
                uint2 bh = __ldg(&g_w1pk_h[base + i * 32]);
                uint2 bl = __ldg(&g_w1pk_l[base + i * 32]);
                MMA16816(acc1[i], Ah, bh.x, bh.y);
                MMA16816(acc1[i], Ah, bl.x, bl.y);
                MMA16816(acc1[i], Al, bh.x, bh.y);
            }
        }
        __syncthreads();                             // S1: prev head fully done with smem
#pragma unroll
        for (int i = 0; i < 8; i++) {
            int col = wn * 64 + i * 8 + gc;
            float c0 = __ldg(&g_c1[hoff + col]), c1v = __ldg(&g_c1[hoff + col + 1]);
            s_h1[r0 * 132 + col]           = gate0 * (acc1[i][0] + c0);
            s_h1[r0 * 132 + col + 1]       = gate0 * (acc1[i][1] + c1v);
            s_h1[(r0 + 8) * 132 + col]     = gate1 * (acc1[i][2] + c0);
            s_h1[(r0 + 8) * 132 + col + 1] = gate1 * (acc1[i][3] + c1v);
        }
        if (t < 64) { s_smax[t] = -1e30f; s_ssum[t] = 0.f; }
        __syncthreads();                             // S2: h1 visible

        // node scores: warp w -> rows w*8..+7
        {
            float a0 = __ldg(&a_src1[hoff + lane * 4]);
            float a1 = __ldg(&a_src1[hoff + lane * 4 + 1]);
            float a2 = __ldg(&a_src1[hoff + lane * 4 + 2]);
            float a3 = __ldg(&a_src1[hoff + lane * 4 + 3]);
            float d0 = __ldg(&a_dst1[hoff + lane * 4]);
            float d1 = __ldg(&a_dst1[hoff + lane * 4 + 1]);
            float d2 = __ldg(&a_dst1[hoff + lane * 4 + 2]);
            float d3 = __ldg(&a_dst1[hoff + lane * 4 + 3]);
#pragma unroll
            for (int j = 0; j < 8; j++) {
                int i = w * 8 + j;
                float4 hv = *(const float4*)(s_h1 + i * 132 + lane * 4);
                float s1 = hv.x * a0 + hv.y * a1 + hv.z * a2 + hv.w * a3;
                float s2 = hv.x * d0 + hv.y * d1 + hv.z * d2 + hv.w * d3;
#pragma unroll
                for (int off = 16; off > 0; off >>= 1) {
                    s1 += __shfl_xor_sync(0xffffffffu, s1, off);
                    s2 += __shfl_xor_sync(0xffffffffu, s2, off);
                }
                if (lane == 0) { s_ssrc[i] = s1; s_sdst[i] = s2; }
            }
        }
        __syncthreads();                             // S3
        if (t < 192) {
            int ed = s_ed[t];
            float sc = s_ssrc[ed & 255] + s_sdst[ed >> 8];
            sc = sc > 0.f ? sc : 0.2f * sc;
            s_eprob[t] = sc;
            atomicMaxFloatS(&s_smax[ed >> 8], sc);
        }
        __syncthreads();                             // S4
        if (t < 192) {
            int tt = s_ed[t] >> 8;
            float p = __expf(s_eprob[t] - s_smax[tt]);
            s_eprob[t] = p;
            atomicAdd(&s_ssum[tt], p);
        }
        __syncthreads();                             // S5
        if (t < 192) {
            int tt = s_ed[t] >> 8;
            s_aprob[s_slot[t]] = s_eprob[t] / (s_ssum[tt] + 1e-16f);
        }
        __syncthreads();                             // S6

        // aggregation + bias + elu -> o1 hi/lo (SMEM only)
        {
            int d = t & 127, half = t >> 7;
            float bd = __ldg(&b1[hoff + d]);
            for (int tt = half * 32; tt < half * 32 + 32; tt++) {
                float a = 0.f;
                int k0 = s_startc[tt], k1 = s_startc[tt + 1];
                for (int k = k0; k < k1; k++)
                    a = fmaf(s_aprob[k], s_h1[s_osrc[k] + d], a);
                float val = a + bd;
                val = val > 0.f ? val : (__expf(val) - 1.f);
                __nv_bfloat16 hi = __float2bfloat16(val);
                s_o1h[tt * 136 + d] = hi;
                s_o1l[tt * 136 + d] = __float2bfloat16(val - __bfloat162float(hi));
            }
        }
        __syncthreads();                             // S7: o1 visible

        // GEMM2 partial: acc2 += o1_head @ W2[head]
        {
            uint32_t aoff = (uint32_t)((wm * 16 + (lane & 15)) * 272 + (lane >> 4) * 16);
#pragma unroll
            for (int kk = 0; kk < 8; kk++) {
                uint32_t Ah[4], Al[4];
                LDSM_X4(Ah[0], Ah[1], Ah[2], Ah[3], sbO1h + aoff + kk * 32);
                LDSM_X4(Al[0], Al[1], Al[2], Al[3], sbO1l + aoff + kk * 32);
                int base = ((h * 8 + kk) * 16 + wn * 8) * 32 + lane;
#pragma unroll
                for (int i = 0; i < 8; i++) {
                    uint2 bh = __ldg(&g_w2pk_h[base + i * 32]);
                    uint2 bl = __ldg(&g_w2pk_l[base + i * 32]);
                    MMA16816(acc2[i], Ah, bh.x, bh.y);
                    MMA16816(acc2[i], Ah, bl.x, bl.y);
                    MMA16816(acc2[i], Al, bh.x, bh.y);
                }
            }
        }
    }
    __syncthreads();

    // ---------- h2 write (reuse h1 region) ----------
#pragma unroll
    for (int i = 0; i < 8; i++) {
        int col = wn * 64 + i * 8 + gc;
        s_h1[r0 * 132 + col]           = acc2[i][0];
        s_h1[r0 * 132 + col + 1]       = acc2[i][1];
        s_h1[(r0 + 8) * 132 + col]     = acc2[i][2];
        s_h1[(r0 + 8) * 132 + col + 1] = acc2[i][3];
    }
    if (t < 64) { s_smax[t] = -1e30f; s_ssum[t] = 0.f; }
    __syncthreads();

    // ---------- GAT2 (1 head) ----------
    {
        float a0 = __ldg(&a_src2[lane * 4]);
        float a1 = __ldg(&a_src2[lane * 4 + 1]);
        float a2 = __ldg(&a_src2[lane * 4 + 2]);
        float a3 = __ldg(&a_src2[lane * 4 + 3]);
        float d0 = __ldg(&a_dst2[lane * 4]);
        float d1 = __ldg(&a_dst2[lane * 4 + 1]);
        float d2 = __ldg(&a_dst2[lane * 4 + 2]);
        float d3 = __ldg(&a_dst2[lane * 4 + 3]);
#pragma unroll
        for (int j = 0; j < 8; j++) {
            int i = w * 8 + j;
            float4 hv = *(const float4*)(s_h1 + i * 132 + lane * 4);
            float s1 = hv.x * a0 + hv.y * a1 + hv.z * a2 + hv.w * a3;
            float s2 = hv.x * d0 + hv.y * d1 + hv.z * d2 + hv.w * d3;
#pragma unroll
            for (int off = 16; off > 0; off >>= 1) {
                s1 += __shfl_xor_sync(0xffffffffu, s1, off);
                s2 += __shfl_xor_sync(0xffffffffu, s2, off);
            }
            if (lane == 0) { s_ssrc[i] = s1; s_sdst[i] = s2; }
        }
    }
    __syncthreads();
    if (t < 192) {
        int ed = s_ed[t];
        float sc = s_ssrc[ed & 255] + s_sdst[ed >> 8];
        sc = sc > 0.f ? sc : 0.2f * sc;
        s_eprob[t] = sc;
        atomicMaxFloatS(&s_smax[ed >> 8], sc);
    }
    __syncthreads();
    if (t < 192) {
        int tt = s_ed[t] >> 8;
        float p = __expf(s_eprob[t] - s_smax[tt]);
        s_eprob[t] = p;
        atomicAdd(&s_ssum[tt], p);
    }
    __syncthreads();
    if (t < 192) {
        int tt = s_ed[t] >> 8;
        s_aprob[s_slot[t]] = s_eprob[t] / (s_ssum[tt] + 1e-16f);
    }
    __syncthreads();
    {
        int d = t & 127, half = t >> 7;
        float bd = __ldg(&b2[d]);
        for (int tt = half * 32; tt < half * 32 + 32; tt++) {
            float a = 0.f;
            int k0 = s_startc[tt], k1 = s_startc[tt + 1];
            for (int k = k0; k < k1; k++)
                a = fmaf(s_aprob[k], s_h1[s_osrc[k] + d], a);
            s_o2[tt * 128 + d] = a + bd;
        }
    }
    __syncthreads();

    // ---------- mean pool + classifier ----------
    if (t < 128) {
        float a = 0.f;
#pragma unroll 8
        for (int i = 0; i < 64; i++) a += s_o2[i * 128 + t];
        s_gv[t] = a * (1.0f / 64.0f);
    }
    __syncthreads();
    if (t < 64) {
        float a = __ldg(&bc1[t]);
#pragma unroll 8
        for (int d = 0; d < 128; d++) a = fmaf(s_gv[d], __ldg(&Wc1[d * 64 + t]), a);
        s_hc[t] = a > 0.f ? a : 0.01f * a;
    }
    __syncthreads();
    if (t < 16) {
        float a = __ldg(&bc2[t]);
#pragma unroll 8
        for (int j = 0; j < 64; j++) a = fmaf(s_hc[j], __ldg(&Wc2[j * 16 + t]), a);
        outp[(size_t)b * 16 + t] = a;
    }
}

// ---------------- launch ----------------
extern "C" void kernel_launch(void* const* d_in, const int* in_sizes, int n_in,
                              void* d_out, int out_size)
{
    const float* emb         = (const float*)d_in[0];
    const int*   edge_index  = (const int*)d_in[1];
    const float* W_align     = (const float*)d_in[3];
    const float* b_align     = (const float*)d_in[4];
    const float* gate_logits = (const float*)d_in[5];
    const float* W1          = (const float*)d_in[6];
    const float* a_src1      = (const float*)d_in[7];
    const float* a_dst1      = (const float*)d_in[8];
    const float* b1          = (const float*)d_in[9];
    const float* W2          = (const float*)d_in[10];
    const float* a_src2      = (const float*)d_in[11];
    const float* a_dst2      = (const float*)d_in[12];
    const float* b2          = (const float*)d_in[13];
    const float* Wc1         = (const float*)d_in[14];
    const float* bc1         = (const float*)d_in[15];
    const float* Wc2         = (const float*)d_in[16];
    const float* bc2         = (const float*)d_in[17];
    float* out = (float*)d_out;

    cudaFuncSetAttribute(mega_kernel, cudaFuncAttributeMaxDynamicSharedMemorySize, MG_DYN);

    float* gate_out = (out_size >= 64) ? (out + (out_size - 64)) : nullptr;

    // 1) weight prep (B-fragment packing) + gate
    prep_weights_kernel<<<163, 256>>>(W_align, W1, W2, b_align, gate_logits, gate_out);

    // 2) emb prep (A-fragment packing, hi/lo)
    prep_emb_kernel<<<2048, 256>>>(emb);

    // 3) fused per-graph pipeline (o1 stays in SMEM)
    mega_kernel<<<B_GRAPHS, 256, MG_DYN>>>(
        edge_index, gate_logits,
        a_src1, a_dst1, b1, a_src2, a_dst2, b2,
        Wc1, bc1, Wc2, bc2, out);
}

// round 8
// speedup vs baseline: 2.5364x; 1.2503x over previous
#include <cuda_runtime.h>
#include <cuda_fp16.h>
#include <math.h>
#include <cstdint>

// ---------------- problem constants ----------------
#define B_GRAPHS 2048
#define F_NODES  64
#define D_IN     32
#define HDIM     128
#define HEADS    4
#define NC       16
#define EPG      128
#define N_NODES  (B_GRAPHS * F_NODES)        // 131072
#define E_EDGES  (B_GRAPHS * EPG)            // 262144

// ---------------- device-global scratch ----------------
// W1' = Wa@W1 in B-fragment layout (fp16 hi/lo): [ks(2)][gnt(64)][lane(32)] -> uint2
__device__ uint2 g_w1pk_h[2 * 64 * 32];
__device__ uint2 g_w1pk_l[2 * 64 * 32];
__device__ float g_c1[512];                   // b_align @ W1
// W2^T in B-fragment layout (fp16 hi/lo): [ks(32)][gnt(16)][lane(32)] -> uint2
__device__ uint2 g_w2pk_h[32 * 16 * 32];
__device__ uint2 g_w2pk_l[32 * 16 * 32];
// emb in A-fragment layout (fp16 hi/lo): [rowgrp(8192)][ks(2)][lane(32)] -> uint4
__device__ uint4 g_embA_h[(size_t)8192 * 2 * 32];
__device__ uint4 g_embA_l[(size_t)8192 * 2 * 32];

// ---------------- PTX helpers (sm_80+; no tcgen05 — ptxas targets compute_103) ----------------
__device__ __forceinline__ uint32_t smem_to_u32(const void* p) {
    uint32_t a;
    asm("{ .reg .u64 tmp; cvta.to.shared.u64 tmp, %1; cvt.u32.u64 %0, tmp; }" : "=r"(a) : "l"(p));
    return a;
}
#define LDSM_X4(r0, r1, r2, r3, addr) \
    asm volatile("ldmatrix.sync.aligned.m8n8.x4.shared.b16 {%0,%1,%2,%3}, [%4];" \
                 : "=r"(r0), "=r"(r1), "=r"(r2), "=r"(r3) : "r"(addr))

#define MMAF16(d, a, b0, b1) \
    asm volatile("mma.sync.aligned.m16n8k16.row.col.f32.f16.f16.f32 " \
                 "{%0,%1,%2,%3}, {%4,%5,%6,%7}, {%8,%9}, {%0,%1,%2,%3};" \
                 : "+f"((d)[0]), "+f"((d)[1]), "+f"((d)[2]), "+f"((d)[3]) \
                 : "r"((a)[0]), "r"((a)[1]), "r"((a)[2]), "r"((a)[3]), "r"(b0), "r"(b1))

__device__ __forceinline__ void atomicMaxFloatS(float* addr, float val) {
    int* ai = (int*)addr;
    int old = *ai;
    while (__int_as_float(old) < val) {
        int assumed = old;
        old = atomicCAS(ai, assumed, __float_as_int(val));
        if (old == assumed) break;
    }
}
// fp16 hi/lo split of a float pair, packed as half2 words
__device__ __forceinline__ void split_pair_h(float a, float b, uint32_t& hi, uint32_t& lo) {
    __half ha = __float2half_rn(a), hb = __float2half_rn(b);
    __half2 H = __halves2half2(ha, hb);
    __half2 L = __halves2half2(__float2half_rn(a - __half2float(ha)),
                               __float2half_rn(b - __half2float(hb)));
    hi = *(uint32_t*)&H;
    lo = *(uint32_t*)&L;
}

// ---------------- prep 1: weights -> B-fragment fp16 layout, + c1 + gate ----------------
__global__ __launch_bounds__(256) void prep_weights_kernel(
    const float* __restrict__ Wa, const float* __restrict__ W1,
    const float* __restrict__ W2, const float* __restrict__ b_align,
    const float* __restrict__ gl, float* __restrict__ gate_out)
{
    int gid = blockIdx.x * 256 + threadIdx.x;
    if (gid < 8192) {
        int wid = gid;
        int reg = wid & 1, lane = (wid >> 1) & 31, gnt = (wid >> 6) & 63, ks = wid >> 12;
        int n = gnt * 8 + (lane >> 2);
        int k = ks * 16 + reg * 8 + (lane & 3) * 2;
        float v0 = 0.f, v1 = 0.f;
#pragma unroll 8
        for (int m = 0; m < 128; m++) {
            v0 = fmaf(Wa[k * 128 + m], W1[m * 512 + n], v0);
            v1 = fmaf(Wa[(k + 1) * 128 + m], W1[m * 512 + n], v1);
        }
        uint32_t hi, lo;
        split_pair_h(v0, v1, hi, lo);
        ((uint32_t*)g_w1pk_h)[wid] = hi;
        ((uint32_t*)g_w1pk_l)[wid] = lo;
    } else if (gid < 40960) {
        int wid = gid - 8192;
        int reg = wid & 1, lane = (wid >> 1) & 31, gnt = (wid >> 6) & 15, ks = wid >> 10;
        int n = gnt * 8 + (lane >> 2);
        int k = ks * 16 + reg * 8 + (lane & 3) * 2;
        uint32_t hi, lo;
        split_pair_h(W2[k * 128 + n], W2[(k + 1) * 128 + n], hi, lo);
        ((uint32_t*)g_w2pk_h)[wid] = hi;
        ((uint32_t*)g_w2pk_l)[wid] = lo;
    } else if (gid < 41472) {
        int n = gid - 40960;
        float acc = 0.f;
#pragma unroll 8
        for (int m = 0; m < 128; m++) acc = fmaf(b_align[m], W1[m * 512 + n], acc);
        g_c1[n] = acc;
    } else if (gid < 41536) {
        int f = gid - 41472;
        if (gate_out != nullptr) gate_out[f] = 1.0f / (1.0f + expf(-gl[f]));
    }
}

// ---------------- prep 2: emb -> A-fragment fp16 layout (hi/lo) ----------------
__global__ __launch_bounds__(256) void prep_emb_kernel(const float* __restrict__ emb)
{
    int gid = blockIdx.x * 256 + threadIdx.x;    // 524288
    int lane = gid & 31;
    int ks = (gid >> 5) & 1;
    int grp = gid >> 6;                          // 0..8191 (16-row groups)
    int gr = lane >> 2, gc = (lane & 3) * 2;
    const float* base = emb + (size_t)grp * 16 * 32 + ks * 16;

    float v0 = base[gr * 32 + gc],           v1 = base[gr * 32 + gc + 1];
    float v2 = base[(gr + 8) * 32 + gc],     v3 = base[(gr + 8) * 32 + gc + 1];
    float v4 = base[gr * 32 + gc + 8],       v5 = base[gr * 32 + gc + 9];
    float v6 = base[(gr + 8) * 32 + gc + 8], v7 = base[(gr + 8) * 32 + gc + 9];

    uint4 H, L;
    split_pair_h(v0, v1, H.x, L.x);
    split_pair_h(v2, v3, H.y, L.y);
    split_pair_h(v4, v5, H.z, L.z);
    split_pair_h(v6, v7, H.w, L.w);
    g_embA_h[gid] = H;
    g_embA_l[gid] = L;
}

// ---------------- mega kernel: one CTA per graph, occupancy 3 ----------------
// dynamic smem: [0,33792) h1/h2 fp32 64x132 | [33792,51200) o1 fp16 64x136
#define MG_O1  33792
#define MG_DYN 51200

__global__ __launch_bounds__(256, 3) void mega_kernel(
    const int* __restrict__ eidx, const float* __restrict__ gl,
    const float* __restrict__ a_src1, const float* __restrict__ a_dst1,
    const float* __restrict__ b1,
    const float* __restrict__ a_src2, const float* __restrict__ a_dst2,
    const float* __restrict__ b2,
    const float* __restrict__ Wc1, const float* __restrict__ bc1,
    const float* __restrict__ Wc2, const float* __restrict__ bc2,
    float* __restrict__ outp)
{
    extern __shared__ __align__(16) char smem[];
    float* s_h1 = (float*)smem;                          // stride 132 fp32
    __half* s_o1 = (__half*)(smem + MG_O1);              // stride 136 fp16
    uint32_t sbO1 = smem_to_u32(smem) + MG_O1;

    __shared__ int   s_ed[192], s_slot[192], s_osrc[192], s_startc[65], s_deg[64], s_cur[64];
    __shared__ float s_eprob[192], s_aprob[192];
    __shared__ float s_ssrc[64], s_sdst[64], s_smax[64], s_ssum[64];
    __shared__ float s_gv[256], s_hc[64];

    int b = blockIdx.x, t = threadIdx.x, lane = t & 31, w = t >> 5;
    int wm = w >> 1, wn = w & 1;
    int gr = lane >> 2, gc = (lane & 3) * 2;
    int node0 = b * 64;
    int r0 = wm * 16 + gr;

    // ---------- phase 0 ----------
    if (t < 64) { s_deg[t] = 0; s_cur[t] = 0; }
    if (t < 192) {
        int src, tt;
        if (t < 128) { src = eidx[b * 128 + t] - node0; tt = eidx[E_EDGES + b * 128 + t] - node0; }
        else         { src = t - 128; tt = src; }
        s_ed[t] = src | (tt << 8);
    }
    float gate0 = 1.0f / (1.0f + __expf(-__ldg(&gl[r0])));
    float gate1 = 1.0f / (1.0f + __expf(-__ldg(&gl[r0 + 8])));

    __syncthreads();
    if (t < 192) atomicAdd(&s_deg[s_ed[t] >> 8], 1);
    __syncthreads();
    if (w == 0) {                                    // warp-scan prefix over 64 degrees
        int v0 = s_deg[lane * 2], v1 = s_deg[lane * 2 + 1];
        int p = v0 + v1, run = p;
#pragma unroll
        for (int off = 1; off < 32; off <<= 1) {
            int n = __shfl_up_sync(0xffffffffu, run, off);
            if (lane >= off) run += n;
        }
        s_startc[lane * 2] = run - p;
        s_startc[lane * 2 + 1] = run - p + v0;
        if (lane == 31) s_startc[64] = run;
    }
    __syncthreads();
    if (t < 192) {
        int tt = s_ed[t] >> 8, src = s_ed[t] & 255;
        int pos = atomicAdd(&s_cur[tt], 1);
        int slot = s_startc[tt] + pos;
        s_slot[t] = slot;
        s_osrc[slot] = src * 132;                    // premultiplied h1 row stride
    }

    float acc2[8][4] = {};                           // persistent GEMM2 accumulator

    // ---------- head loop: GEMM1 (3-pass) -> GAT1 -> GEMM2 partial (2-pass) ----------
    for (int h = 0; h < HEADS; h++) {
        int hoff = h * 128;
        int grp = b * 4 + wm;

        float acc1[8][4] = {};
#pragma unroll
        for (int ks = 0; ks < 2; ks++) {
            uint4 H4 = __ldg(&g_embA_h[(size_t)(grp * 2 + ks) * 32 + lane]);
            uint4 L4 = __ldg(&g_embA_l[(size_t)(grp * 2 + ks) * 32 + lane]);
            uint32_t Ah[4] = { H4.x, H4.y, H4.z, H4.w };
            uint32_t Al[4] = { L4.x, L4.y, L4.z, L4.w };
            int base = (ks * 64 + h * 16 + wn * 8) * 32 + lane;
#pragma unroll
            for (int i = 0; i < 8; i++) {
                uint2 bh = __ldg(&g_w1pk_h[base + i * 32]);
                uint2 bl = __ldg(&g_w1pk_l[base + i * 32]);
                MMAF16(acc1[i], Ah, bh.x, bh.y);
                MMAF16(acc1[i], Ah, bl.x, bl.y);
                MMAF16(acc1[i], Al, bh.x, bh.y);
            }
        }
        __syncthreads();                             // S1: prev head done with smem
#pragma unroll
        for (int i = 0; i < 8; i++) {
            int col = wn * 64 + i * 8 + gc;
            float c0 = __ldg(&g_c1[hoff + col]), c1v = __ldg(&g_c1[hoff + col + 1]);
            s_h1[r0 * 132 + col]           = gate0 * (acc1[i][0] + c0);
            s_h1[r0 * 132 + col + 1]       = gate0 * (acc1[i][1] + c1v);
            s_h1[(r0 + 8) * 132 + col]     = gate1 * (acc1[i][2] + c0);
            s_h1[(r0 + 8) * 132 + col + 1] = gate1 * (acc1[i][3] + c1v);
        }
        if (t < 64) { s_smax[t] = -1e30f; s_ssum[t] = 0.f; }
        __syncthreads();                             // S2: h1 visible

        // node scores
        {
            float a0 = __ldg(&a_src1[hoff + lane * 4]);
            float a1 = __ldg(&a_src1[hoff + lane * 4 + 1]);
            float a2 = __ldg(&a_src1[hoff + lane * 4 + 2]);
            float a3 = __ldg(&a_src1[hoff + lane * 4 + 3]);
            float d0 = __ldg(&a_dst1[hoff + lane * 4]);
            float d1 = __ldg(&a_dst1[hoff + lane * 4 + 1]);
            float d2 = __ldg(&a_dst1[hoff + lane * 4 + 2]);
            float d3 = __ldg(&a_dst1[hoff + lane * 4 + 3]);
#pragma unroll
            for (int j = 0; j < 8; j++) {
                int i = w * 8 + j;
                float4 hv = *(const float4*)(s_h1 + i * 132 + lane * 4);
                float s1 = hv.x * a0 + hv.y * a1 + hv.z * a2 + hv.w * a3;
                float s2 = hv.x * d0 + hv.y * d1 + hv.z * d2 + hv.w * d3;
#pragma unroll
                for (int off = 16; off > 0; off >>= 1) {
                    s1 += __shfl_xor_sync(0xffffffffu, s1, off);
                    s2 += __shfl_xor_sync(0xffffffffu, s2, off);
                }
                if (lane == 0) { s_ssrc[i] = s1; s_sdst[i] = s2; }
            }
        }
        __syncthreads();                             // S3
        if (t < 192) {
            int ed = s_ed[t];
            float sc = s_ssrc[ed & 255] + s_sdst[ed >> 8];
            sc = sc > 0.f ? sc : 0.2f * sc;
            s_eprob[t] = sc;
            atomicMaxFloatS(&s_smax[ed >> 8], sc);
        }
        __syncthreads();                             // S4
        if (t < 192) {
            int tt = s_ed[t] >> 8;
            float p = __expf(s_eprob[t] - s_smax[tt]);
            s_eprob[t] = p;
            atomicAdd(&s_ssum[tt], p);
        }
        __syncthreads();                             // S5
        if (t < 192) {
            int tt = s_ed[t] >> 8;
            s_aprob[s_slot[t]] = s_eprob[t] / (s_ssum[tt] + 1e-16f);
        }
        __syncthreads();                             // S6

        // aggregation + bias + elu -> o1 (single-rounded fp16, SMEM only)
        {
            int d = t & 127, half = t >> 7;
            float bd = __ldg(&b1[hoff + d]);
            for (int tt = half * 32; tt < half * 32 + 32; tt++) {
                float a = 0.f;
                int k0 = s_startc[tt], k1 = s_startc[tt + 1];
                for (int k = k0; k < k1; k++)
                    a = fmaf(s_aprob[k], s_h1[s_osrc[k] + d], a);
                float val = a + bd;
                val = val > 0.f ? val : (__expf(val) - 1.f);
                s_o1[tt * 136 + d] = __float2half_rn(val);
            }
        }
        __syncthreads();                             // S7: o1 visible

        // GEMM2 partial (2-pass): acc2 += o1_head @ W2[head]
        {
            uint32_t aoff = (uint32_t)((wm * 16 + (lane & 15)) * 272 + (lane >> 4) * 16);
#pragma unroll
            for (int kk = 0; kk < 8; kk++) {
                uint32_t Ah[4];
                LDSM_X4(Ah[0], Ah[1], Ah[2], Ah[3], sbO1 + aoff + kk * 32);
                int base = ((h * 8 + kk) * 16 + wn * 8) * 32 + lane;
#pragma unroll
                for (int i = 0; i < 8; i++) {
                    uint2 bh = __ldg(&g_w2pk_h[base + i * 32]);
                    uint2 bl = __ldg(&g_w2pk_l[base + i * 32]);
                    MMAF16(acc2[i], Ah, bh.x, bh.y);
                    MMAF16(acc2[i], Ah, bl.x, bl.y);
                }
            }
        }
    }
    __syncthreads();

    // ---------- h2 write (reuse h1 region) ----------
#pragma unroll
    for (int i = 0; i < 8; i++) {
        int col = wn * 64 + i * 8 + gc;
        s_h1[r0 * 132 + col]           = acc2[i][0];
        s_h1[r0 * 132 + col + 1]       = acc2[i][1];
        s_h1[(r0 + 8) * 132 + col]     = acc2[i][2];
        s_h1[(r0 + 8) * 132 + col + 1] = acc2[i][3];
    }
    if (t < 64) { s_smax[t] = -1e30f; s_ssum[t] = 0.f; }
    __syncthreads();

    // ---------- GAT2 (1 head) ----------
    {
        float a0 = __ldg(&a_src2[lane * 4]);
        float a1 = __ldg(&a_src2[lane * 4 + 1]);
        float a2 = __ldg(&a_src2[lane * 4 + 2]);
        float a3 = __ldg(&a_src2[lane * 4 + 3]);
        float d0 = __ldg(&a_dst2[lane * 4]);
        float d1 = __ldg(&a_dst2[lane * 4 + 1]);
        float d2 = __ldg(&a_dst2[lane * 4 + 2]);
        float d3 = __ldg(&a_dst2[lane * 4 + 3]);
#pragma unroll
        for (int j = 0; j < 8; j++) {
            int i = w * 8 + j;
            float4 hv = *(const float4*)(s_h1 + i * 132 + lane * 4);
            float s1 = hv.x * a0 + hv.y * a1 + hv.z * a2 + hv.w * a3;
            float s2 = hv.x * d0 + hv.y * d1 + hv.z * d2 + hv.w * d3;
#pragma unroll
            for (int off = 16; off > 0; off >>= 1) {
                s1 += __shfl_xor_sync(0xffffffffu, s1, off);
                s2 += __shfl_xor_sync(0xffffffffu, s2, off);
            }
            if (lane == 0) { s_ssrc[i] = s1; s_sdst[i] = s2; }
        }
    }
    __syncthreads();
    if (t < 192) {
        int ed = s_ed[t];
        float sc = s_ssrc[ed & 255] + s_sdst[ed >> 8];
        sc = sc > 0.f ? sc : 0.2f * sc;
        s_eprob[t] = sc;
        atomicMaxFloatS(&s_smax[ed >> 8], sc);
    }
    __syncthreads();
    if (t < 192) {
        int tt = s_ed[t] >> 8;
        float p = __expf(s_eprob[t] - s_smax[tt]);
        s_eprob[t] = p;
        atomicAdd(&s_ssum[tt], p);
    }
    __syncthreads();
    if (t < 192) {
        int tt = s_ed[t] >> 8;
        s_aprob[s_slot[t]] = s_eprob[t] / (s_ssum[tt] + 1e-16f);
    }
    __syncthreads();

    // GAT2 aggregation fused with mean pool: o2 never materialized
    {
        int d = t & 127, half = t >> 7;
        float psum = 0.f;
        for (int tt = half * 32; tt < half * 32 + 32; tt++) {
            float a = 0.f;
            int k0 = s_startc[tt], k1 = s_startc[tt + 1];
            for (int k = k0; k < k1; k++)
                a = fmaf(s_aprob[k], s_h1[s_osrc[k] + d], a);
            psum += a;
        }
        s_gv[half * 128 + d] = psum;
    }
    __syncthreads();

    // ---------- classifier ----------
    if (t < 128) {
        // mean over 64 rows; b2 adds once per row -> +b2[d] after /64
        s_gv[t] = (s_gv[t] + s_gv[128 + t]) * (1.0f / 64.0f) + __ldg(&b2[t]);
    }
    __syncthreads();
    if (t < 64) {
        float a = __ldg(&bc1[t]);
#pragma unroll 8
        for (int d = 0; d < 128; d++) a = fmaf(s_gv[d], __ldg(&Wc1[d * 64 + t]), a);
        s_hc[t] = a > 0.f ? a : 0.01f * a;
    }
    __syncthreads();
    if (t < 16) {
        float a = __ldg(&bc2[t]);
#pragma unroll 8
        for (int j = 0; j < 64; j++) a = fmaf(s_hc[j], __ldg(&Wc2[j * 16 + t]), a);
        outp[(size_t)b * 16 + t] = a;
    }
}

// ---------------- launch ----------------
extern "C" void kernel_launch(void* const* d_in, const int* in_sizes, int n_in,
                              void* d_out, int out_size)
{
    const float* emb         = (const float*)d_in[0];
    const int*   edge_index  = (const int*)d_in[1];
    const float* W_align     = (const float*)d_in[3];
    const float* b_align     = (const float*)d_in[4];
    const float* gate_logits = (const float*)d_in[5];
    const float* W1          = (const float*)d_in[6];
    const float* a_src1      = (const float*)d_in[7];
    const float* a_dst1      = (const float*)d_in[8];
    const float* b1          = (const float*)d_in[9];
    const float* W2          = (const float*)d_in[10];
    const float* a_src2      = (const float*)d_in[11];
    const float* a_dst2      = (const float*)d_in[12];
    const float* b2          = (const float*)d_in[13];
    const float* Wc1         = (const float*)d_in[14];
    const float* bc1         = (const float*)d_in[15];
    const float* Wc2         = (const float*)d_in[16];
    const float* bc2         = (const float*)d_in[17];
    float* out = (float*)d_out;

    cudaFuncSetAttribute(mega_kernel, cudaFuncAttributeMaxDynamicSharedMemorySize, MG_DYN);

    float* gate_out = (out_size >= 64) ? (out + (out_size - 64)) : nullptr;

    // 1) weight prep (fp16 B-fragment packing) + gate
    prep_weights_kernel<<<163, 256>>>(W_align, W1, W2, b_align, gate_logits, gate_out);

    // 2) emb prep (fp16 A-fragment packing, hi/lo)
    prep_emb_kernel<<<2048, 256>>>(emb);

    // 3) fused per-graph pipeline (o1 stays in SMEM), occupancy 3
    mega_kernel<<<B_GRAPHS, 256, MG_DYN>>>(
        edge_index, gate_logits,
        a_src1, a_dst1, b1, a_src2, a_dst2, b2,
        Wc1, bc1, Wc2, bc2, out);
}

// round 9
// speedup vs baseline: 3.6419x; 1.4359x over previous
#include <cuda_runtime.h>
#include <cuda_fp16.h>
#include <math.h>
#include <cstdint>

// ---------------- problem constants ----------------
#define B_GRAPHS 2048
#define F_NODES  64
#define D_IN     32
#define HDIM     128
#define HEADS    4
#define NC       16
#define EPG      128
#define N_NODES  (B_GRAPHS * F_NODES)        // 131072
#define E_EDGES  (B_GRAPHS * EPG)            // 262144

// ---------------- device-global scratch ----------------
// W1' = Wa@W1 in B-fragment layout (single fp16): [ks(2)][gnt(64)][lane(32)] -> uint2
__device__ uint2 g_w1pk[2 * 64 * 32];
__device__ float g_c1[512];                   // b_align @ W1
// W2^T in B-fragment layout (single fp16): [ks(32)][gnt(16)][lane(32)] -> uint2
__device__ uint2 g_w2pk[32 * 16 * 32];
// emb in A-fragment layout (fp16 hi/lo): [rowgrp(8192)][ks(2)][lane(32)] -> uint4
__device__ uint4 g_embA_h[(size_t)8192 * 2 * 32];
__device__ uint4 g_embA_l[(size_t)8192 * 2 * 32];

// ---------------- PTX helpers (sm_80+; no tcgen05 — ptxas targets compute_103) ----------------
__device__ __forceinline__ uint32_t smem_to_u32(const void* p) {
    uint32_t a;
    asm("{ .reg .u64 tmp; cvta.to.shared.u64 tmp, %1; cvt.u32.u64 %0, tmp; }" : "=r"(a) : "l"(p));
    return a;
}
#define LDSM_X4(r0, r1, r2, r3, addr) \
    asm volatile("ldmatrix.sync.aligned.m8n8.x4.shared.b16 {%0,%1,%2,%3}, [%4];" \
                 : "=r"(r0), "=r"(r1), "=r"(r2), "=r"(r3) : "r"(addr))

#define MMAF16(d, a, b0, b1) \
    asm volatile("mma.sync.aligned.m16n8k16.row.col.f32.f16.f16.f32 " \
                 "{%0,%1,%2,%3}, {%4,%5,%6,%7}, {%8,%9}, {%0,%1,%2,%3};" \
                 : "+f"((d)[0]), "+f"((d)[1]), "+f"((d)[2]), "+f"((d)[3]) \
                 : "r"((a)[0]), "r"((a)[1]), "r"((a)[2]), "r"((a)[3]), "r"(b0), "r"(b1))

__device__ __forceinline__ void atomicMaxFloatS(float* addr, float val) {
    int* ai = (int*)addr;
    int old = *ai;
    while (__int_as_float(old) < val) {
        int assumed = old;
        old = atomicCAS(ai, assumed, __float_as_int(val));
        if (old == assumed) break;
    }
}
__device__ __forceinline__ uint32_t pack_h2(float a, float b) {
    __half2 v = __halves2half2(__float2half_rn(a), __float2half_rn(b));
    return *(uint32_t*)&v;
}
__device__ __forceinline__ void split_pair_h(float a, float b, uint32_t& hi, uint32_t& lo) {
    __half ha = __float2half_rn(a), hb = __float2half_rn(b);
    __half2 H = __halves2half2(ha, hb);
    __half2 L = __halves2half2(__float2half_rn(a - __half2float(ha)),
                               __float2half_rn(b - __half2float(hb)));
    hi = *(uint32_t*)&H;
    lo = *(uint32_t*)&L;
}

// ---------------- prep 1: weights -> B-fragment fp16 layout, + c1 + gate ----------------
__global__ __launch_bounds__(256) void prep_weights_kernel(
    const float* __restrict__ Wa, const float* __restrict__ W1,
    const float* __restrict__ W2, const float* __restrict__ b_align,
    const float* __restrict__ gl, float* __restrict__ gate_out)
{
    int gid = blockIdx.x * 256 + threadIdx.x;
    if (gid < 8192) {
        int wid = gid;
        int reg = wid & 1, lane = (wid >> 1) & 31, gnt = (wid >> 6) & 63, ks = wid >> 12;
        int n = gnt * 8 + (lane >> 2);
        int k = ks * 16 + reg * 8 + (lane & 3) * 2;
        float v0 = 0.f, v1 = 0.f;
#pragma unroll 8
        for (int m = 0; m < 128; m++) {
            v0 = fmaf(Wa[k * 128 + m], W1[m * 512 + n], v0);
            v1 = fmaf(Wa[(k + 1) * 128 + m], W1[m * 512 + n], v1);
        }
        ((uint32_t*)g_w1pk)[wid] = pack_h2(v0, v1);
    } else if (gid < 40960) {
        int wid = gid - 8192;
        int reg = wid & 1, lane = (wid >> 1) & 31, gnt = (wid >> 6) & 15, ks = wid >> 10;
        int n = gnt * 8 + (lane >> 2);
        int k = ks * 16 + reg * 8 + (lane & 3) * 2;
        ((uint32_t*)g_w2pk)[wid] = pack_h2(W2[k * 128 + n], W2[(k + 1) * 128 + n]);
    } else if (gid < 41472) {
        int n = gid - 40960;
        float acc = 0.f;
#pragma unroll 8
        for (int m = 0; m < 128; m++) acc = fmaf(b_align[m], W1[m * 512 + n], acc);
        g_c1[n] = acc;
    } else if (gid < 41536) {
        int f = gid - 41472;
        if (gate_out != nullptr) gate_out[f] = 1.0f / (1.0f + expf(-gl[f]));
    }
}

// ---------------- prep 2: emb -> A-fragment fp16 layout (hi/lo) ----------------
__global__ __launch_bounds__(256) void prep_emb_kernel(const float* __restrict__ emb)
{
    int gid = blockIdx.x * 256 + threadIdx.x;    // 524288
    int lane = gid & 31;
    int ks = (gid >> 5) & 1;
    int grp = gid >> 6;                          // 0..8191 (16-row groups)
    int gr = lane >> 2, gc = (lane & 3) * 2;
    const float* base = emb + (size_t)grp * 16 * 32 + ks * 16;

    float v0 = base[gr * 32 + gc],           v1 = base[gr * 32 + gc + 1];
    float v2 = base[(gr + 8) * 32 + gc],     v3 = base[(gr + 8) * 32 + gc + 1];
    float v4 = base[gr * 32 + gc + 8],       v5 = base[gr * 32 + gc + 9];
    float v6 = base[(gr + 8) * 32 + gc + 8], v7 = base[(gr + 8) * 32 + gc + 9];

    uint4 H, L;
    split_pair_h(v0, v1, H.x, L.x);
    split_pair_h(v2, v3, H.y, L.y);
    split_pair_h(v4, v5, H.z, L.z);
    split_pair_h(v6, v7, H.w, L.w);
    g_embA_h[gid] = H;
    g_embA_l[gid] = L;
}

// ---------------- mega kernel: one CTA per graph, occupancy 3 ----------------
// dynamic smem: [0,33792) h1/h2 fp32 64x132 | [33792,51200) o1 fp16 64x136
#define MG_O1  33792
#define MG_DYN 51200

__global__ __launch_bounds__(256, 3) void mega_kernel(
    const int* __restrict__ eidx, const float* __restrict__ gl,
    const float* __restrict__ a_src1, const float* __restrict__ a_dst1,
    const float* __restrict__ b1,
    const float* __restrict__ a_src2, const float* __restrict__ a_dst2,
    const float* __restrict__ b2,
    const float* __restrict__ Wc1, const float* __restrict__ bc1,
    const float* __restrict__ Wc2, const float* __restrict__ bc2,
    float* __restrict__ outp)
{
    extern __shared__ __align__(16) char smem[];
    float* s_h1 = (float*)smem;                          // stride 132 fp32
    __half* s_o1 = (__half*)(smem + MG_O1);              // stride 136 fp16
    uint32_t sbO1 = smem_to_u32(smem) + MG_O1;

    __shared__ int   s_ed[192], s_slot[192], s_osrc[192], s_startc[65], s_deg[64], s_cur[64];
    __shared__ float s_eprob[192], s_aprob[192];
    __shared__ float s_ssrc[64], s_sdst[64], s_smax[64], s_ssum[64];
    __shared__ float s_gv[512], s_hc[64];

    int b = blockIdx.x, t = threadIdx.x, lane = t & 31, w = t >> 5;
    int wm = w >> 1, wn = w & 1;
    int gr = lane >> 2, gc = (lane & 3) * 2;
    int node0 = b * 64;
    int r0 = wm * 16 + gr;

    // ---------- phase 0 ----------
    if (t < 64) { s_deg[t] = 0; s_cur[t] = 0; }
    if (t < 192) {
        int src, tt;
        if (t < 128) { src = eidx[b * 128 + t] - node0; tt = eidx[E_EDGES + b * 128 + t] - node0; }
        else         { src = t - 128; tt = src; }
        s_ed[t] = src | (tt << 8);
    }
    float gate0 = 1.0f / (1.0f + __expf(-__ldg(&gl[r0])));
    float gate1 = 1.0f / (1.0f + __expf(-__ldg(&gl[r0 + 8])));

    __syncthreads();
    if (t < 192) atomicAdd(&s_deg[s_ed[t] >> 8], 1);
    __syncthreads();
    if (w == 0) {                                    // warp-scan prefix over 64 degrees
        int v0 = s_deg[lane * 2], v1 = s_deg[lane * 2 + 1];
        int p = v0 + v1, run = p;
#pragma unroll
        for (int off = 1; off < 32; off <<= 1) {
            int n = __shfl_up_sync(0xffffffffu, run, off);
            if (lane >= off) run += n;
        }
        s_startc[lane * 2] = run - p;
        s_startc[lane * 2 + 1] = run - p + v0;
        if (lane == 31) s_startc[64] = run;
    }
    __syncthreads();
    if (t < 192) {
        int tt = s_ed[t] >> 8, src = s_ed[t] & 255;
        int pos = atomicAdd(&s_cur[tt], 1);
        int slot = s_startc[tt] + pos;
        s_slot[t] = slot;
        s_osrc[slot] = src * 132;                    // premultiplied h1 row stride
    }

    float acc2[8][4] = {};                           // persistent GEMM2 accumulator

    // ---------- head loop: GEMM1 (2-pass) -> GAT1 -> GEMM2 partial (1-pass) ----------
    for (int h = 0; h < HEADS; h++) {
        int hoff = h * 128;
        int grp = b * 4 + wm;

        float acc1[8][4] = {};
#pragma unroll
        for (int ks = 0; ks < 2; ks++) {
            uint4 H4 = __ldg(&g_embA_h[(size_t)(grp * 2 + ks) * 32 + lane]);
            uint4 L4 = __ldg(&g_embA_l[(size_t)(grp * 2 + ks) * 32 + lane]);
            uint32_t Ah[4] = { H4.x, H4.y, H4.z, H4.w };
            uint32_t Al[4] = { L4.x, L4.y, L4.z, L4.w };
            int base = (ks * 64 + h * 16 + wn * 8) * 32 + lane;
#pragma unroll
            for (int i = 0; i < 8; i++) {
                uint2 bw = __ldg(&g_w1pk[base + i * 32]);
                MMAF16(acc1[i], Ah, bw.x, bw.y);
                MMAF16(acc1[i], Al, bw.x, bw.y);
            }
        }
        __syncthreads();                             // S1: prev head done with smem
#pragma unroll
        for (int i = 0; i < 8; i++) {
            int col = wn * 64 + i * 8 + gc;
            float c0 = __ldg(&g_c1[hoff + col]), c1v = __ldg(&g_c1[hoff + col + 1]);
            s_h1[r0 * 132 + col]           = gate0 * (acc1[i][0] + c0);
            s_h1[r0 * 132 + col + 1]       = gate0 * (acc1[i][1] + c1v);
            s_h1[(r0 + 8) * 132 + col]     = gate1 * (acc1[i][2] + c0);
            s_h1[(r0 + 8) * 132 + col + 1] = gate1 * (acc1[i][3] + c1v);
        }
        if (t < 64) { s_smax[t] = -1e30f; s_ssum[t] = 0.f; }
        __syncthreads();                             // S2: h1 visible

        // node scores
        {
            float a0 = __ldg(&a_src1[hoff + lane * 4]);
            float a1 = __ldg(&a_src1[hoff + lane * 4 + 1]);
            float a2 = __ldg(&a_src1[hoff + lane * 4 + 2]);
            float a3 = __ldg(&a_src1[hoff + lane * 4 + 3]);
            float d0 = __ldg(&a_dst1[hoff + lane * 4]);
            float d1 = __ldg(&a_dst1[hoff + lane * 4 + 1]);
            float d2 = __ldg(&a_dst1[hoff + lane * 4 + 2]);
            float d3 = __ldg(&a_dst1[hoff + lane * 4 + 3]);
#pragma unroll
            for (int j = 0; j < 8; j++) {
                int i = w * 8 + j;
                float4 hv = *(const float4*)(s_h1 + i * 132 + lane * 4);
                float s1 = hv.x * a0 + hv.y * a1 + hv.z * a2 + hv.w * a3;
                float s2 = hv.x * d0 + hv.y * d1 + hv.z * d2 + hv.w * d3;
#pragma unroll
                for (int off = 16; off > 0; off >>= 1) {
                    s1 += __shfl_xor_sync(0xffffffffu, s1, off);
                    s2 += __shfl_xor_sync(0xffffffffu, s2, off);
                }
                if (lane == 0) { s_ssrc[i] = s1; s_sdst[i] = s2; }
            }
        }
        __syncthreads();                             // S3
        if (t < 192) {
            int ed = s_ed[t];
            float sc = s_ssrc[ed & 255] + s_sdst[ed >> 8];
            sc = sc > 0.f ? sc : 0.2f * sc;
            s_eprob[t] = sc;
            atomicMaxFloatS(&s_smax[ed >> 8], sc);
        }
        __syncthreads();                             // S4
        if (t < 192) {
            int tt = s_ed[t] >> 8;
            float p = __expf(s_eprob[t] - s_smax[tt]);
            s_eprob[t] = p;
            atomicAdd(&s_ssum[tt], p);
        }
        __syncthreads();                             // S5
        if (t < 192) {
            int tt = s_ed[t] >> 8;
            s_aprob[s_slot[t]] = s_eprob[t] / (s_ssum[tt] + 1e-16f);
        }
        __syncthreads();                             // S6

        // aggregation + bias + elu -> o1 (single fp16); float2-vectorized
        {
            int q = t >> 6;                          // quarter: 16 targets each
            int d = (t & 63) * 2;
            float b0 = __ldg(&b1[hoff + d]), b1v = __ldg(&b1[hoff + d + 1]);
            for (int tt = q * 16; tt < q * 16 + 16; tt++) {
                float ax = 0.f, ay = 0.f;
                int k0 = s_startc[tt], k1 = s_startc[tt + 1];
                for (int k = k0; k < k1; k++) {
                    float p = s_aprob[k];
                    float2 v = *(const float2*)(s_h1 + s_osrc[k] + d);
                    ax = fmaf(p, v.x, ax);
                    ay = fmaf(p, v.y, ay);
                }
                float vx = ax + b0, vy = ay + b1v;
                vx = vx > 0.f ? vx : (__expf(vx) - 1.f);
                vy = vy > 0.f ? vy : (__expf(vy) - 1.f);
                *(__half2*)(s_o1 + tt * 136 + d) =
                    __halves2half2(__float2half_rn(vx), __float2half_rn(vy));
            }
        }
        __syncthreads();                             // S7: o1 visible

        // GEMM2 partial (1-pass): acc2 += o1_head @ W2[head]
        {
            uint32_t aoff = (uint32_t)((wm * 16 + (lane & 15)) * 272 + (lane >> 4) * 16);
#pragma unroll
            for (int kk = 0; kk < 8; kk++) {
                uint32_t Ah[4];
                LDSM_X4(Ah[0], Ah[1], Ah[2], Ah[3], sbO1 + aoff + kk * 32);
                int base = ((h * 8 + kk) * 16 + wn * 8) * 32 + lane;
#pragma unroll
                for (int i = 0; i < 8; i++) {
                    uint2 bw = __ldg(&g_w2pk[base + i * 32]);
                    MMAF16(acc2[i], Ah, bw.x, bw.y);
                }
            }
        }
    }
    __syncthreads();

    // ---------- h2 write (reuse h1 region) ----------
#pragma unroll
    for (int i = 0; i < 8; i++) {
        int col = wn * 64 + i * 8 + gc;
        s_h1[r0 * 132 + col]           = acc2[i][0];
        s_h1[r0 * 132 + col + 1]       = acc2[i][1];
        s_h1[(r0 + 8) * 132 + col]     = acc2[i][2];
        s_h1[(r0 + 8) * 132 + col + 1] = acc2[i][3];
    }
    if (t < 64) { s_smax[t] = -1e30f; s_ssum[t] = 0.f; }
    __syncthreads();

    // ---------- GAT2 (1 head) ----------
    {
        float a0 = __ldg(&a_src2[lane * 4]);
        float a1 = __ldg(&a_src2[lane * 4 + 1]);
        float a2 = __ldg(&a_src2[lane * 4 + 2]);
        float a3 = __ldg(&a_src2[lane * 4 + 3]);
        float d0 = __ldg(&a_dst2[lane * 4]);
        float d1 = __ldg(&a_dst2[lane * 4 + 1]);
        float d2 = __ldg(&a_dst2[lane * 4 + 2]);
        float d3 = __ldg(&a_dst2[lane * 4 + 3]);
#pragma unroll
        for (int j = 0; j < 8; j++) {
            int i = w * 8 + j;
            float4 hv = *(const float4*)(s_h1 + i * 132 + lane * 4);
            float s1 = hv.x * a0 + hv.y * a1 + hv.z * a2 + hv.w * a3;
            float s2 = hv.x * d0 + hv.y * d1 + hv.z * d2 + hv.w * d3;
#pragma unroll
            for (int off = 16; off > 0; off >>= 1) {
                s1 += __shfl_xor_sync(0xffffffffu, s1, off);
                s2 += __shfl_xor_sync(0xffffffffu, s2, off);
            }
            if (lane == 0) { s_ssrc[i] = s1; s_sdst[i] = s2; }
        }
    }
    __syncthreads();
    if (t < 192) {
        int ed = s_ed[t];
        float sc = s_ssrc[ed & 255] + s_sdst[ed >> 8];
        sc = sc > 0.f ? sc : 0.2f * sc;
        s_eprob[t] = sc;
        atomicMaxFloatS(&s_smax[ed >> 8], sc);
    }
    __syncthreads();
    if (t < 192) {
        int tt = s_ed[t] >> 8;
        float p = __expf(s_eprob[t] - s_smax[tt]);
        s_eprob[t] = p;
        atomicAdd(&s_ssum[tt], p);
    }
    __syncthreads();
    if (t < 192) {
        int tt = s_ed[t] >> 8;
        s_aprob[s_slot[t]] = s_eprob[t] / (s_ssum[tt] + 1e-16f);
    }
    __syncthreads();

    // GAT2 aggregation fused with mean pool (float2); o2 never materialized
    {
        int q = t >> 6;
        int d = (t & 63) * 2;
        float px = 0.f, py = 0.f;
        for (int tt = q * 16; tt < q * 16 + 16; tt++) {
            float ax = 0.f, ay = 0.f;
            int k0 = s_startc[tt], k1 = s_startc[tt + 1];
            for (int k = k0; k < k1; k++) {
                float p = s_aprob[k];
                float2 v = *(const float2*)(s_h1 + s_osrc[k] + d);
                ax = fmaf(p, v.x, ax);
                ay = fmaf(p, v.y, ay);
            }
            px += ax; py += ay;
        }
        s_gv[q * 128 + d] = px;
        s_gv[q * 128 + d + 1] = py;
    }
    __syncthreads();

    // ---------- classifier ----------
    if (t < 128) {
        float g = (s_gv[t] + s_gv[128 + t] + s_gv[256 + t] + s_gv[384 + t]) * (1.0f / 64.0f)
                  + __ldg(&b2[t]);
        s_gv[t] = g;
    }
    __syncthreads();
    if (t < 64) {
        float a = __ldg(&bc1[t]);
#pragma unroll 8
        for (int d = 0; d < 128; d++) a = fmaf(s_gv[d], __ldg(&Wc1[d * 64 + t]), a);
        s_hc[t] = a > 0.f ? a : 0.01f * a;
    }
    __syncthreads();
    if (t < 16) {
        float a = __ldg(&bc2[t]);
#pragma unroll 8
        for (int j = 0; j < 64; j++) a = fmaf(s_hc[j], __ldg(&Wc2[j * 16 + t]), a);
        outp[(size_t)b * 16 + t] = a;
    }
}

// ---------------- launch ----------------
extern "C" void kernel_launch(void* const* d_in, const int* in_sizes, int n_in,
                              void* d_out, int out_size)
{
    const float* emb         = (const float*)d_in[0];
    const int*   edge_index  = (const int*)d_in[1];
    const float* W_align     = (const float*)d_in[3];
    const float* b_align     = (const float*)d_in[4];
    const float* gate_logits = (const float*)d_in[5];
    const float* W1          = (const float*)d_in[6];
    const float* a_src1      = (const float*)d_in[7];
    const float* a_dst1      = (const float*)d_in[8];
    const float* b1          = (const float*)d_in[9];
    const float* W2          = (const float*)d_in[10];
    const float* a_src2      = (const float*)d_in[11];
    const float* a_dst2      = (const float*)d_in[12];
    const float* b2          = (const float*)d_in[13];
    const float* Wc1         = (const float*)d_in[14];
    const float* bc1         = (const float*)d_in[15];
    const float* Wc2         = (const float*)d_in[16];
    const float* bc2         = (const float*)d_in[17];
    float* out = (float*)d_out;

    cudaFuncSetAttribute(mega_kernel, cudaFuncAttributeMaxDynamicSharedMemorySize, MG_DYN);

    float* gate_out = (out_size >= 64) ? (out + (out_size - 64)) : nullptr;

    // 1) weight prep (single-fp16 B-fragment packing) + gate
    prep_weights_kernel<<<163, 256>>>(W_align, W1, W2, b_align, gate_logits, gate_out);

    // 2) emb prep (fp16 A-fragment packing, hi/lo)
    prep_emb_kernel<<<2048, 256>>>(emb);

    // 3) fused per-graph pipeline (o1 stays in SMEM), occupancy 3
    mega_kernel<<<B_GRAPHS, 256, MG_DYN>>>(
        edge_index, gate_logits,
        a_src1, a_dst1, b1, a_src2, a_dst2, b2,
        Wc1, bc1, Wc2, bc2, out);
}

// round 10
// speedup vs baseline: 3.7268x; 1.0233x over previous
#include <cuda_runtime.h>
#include <cuda_fp16.h>
#include <math.h>
#include <cstdint>

// ---------------- problem constants ----------------
#define B_GRAPHS 2048
#define F_NODES  64
#define D_IN     32
#define HDIM     128
#define HEADS    4
#define NC       16
#define EPG      128
#define N_NODES  (B_GRAPHS * F_NODES)        // 131072
#define E_EDGES  (B_GRAPHS * EPG)            // 262144

// ---------------- device-global scratch ----------------
__device__ uint2 g_w1pk[2 * 64 * 32];         // W1'=Wa@W1 B-frag fp16
__device__ float g_c1[512];                   // b_align @ W1
__device__ uint2 g_w2pk[32 * 16 * 32];        // W2^T B-frag fp16
__device__ uint4 g_embA_h[(size_t)8192 * 2 * 32];  // emb A-frag hi
__device__ uint4 g_embA_l[(size_t)8192 * 2 * 32];  // emb A-frag lo
__device__ float g_w1a[8 * 32];               // [sel*4+h][32] = Wa@(W1@a)
__device__ float g_c1a[8];                    // c1 · a

// ---------------- PTX helpers (sm_80+; no tcgen05 — ptxas targets compute_103) ----------------
__device__ __forceinline__ uint32_t smem_to_u32(const void* p) {
    uint32_t a;
    asm("{ .reg .u64 tmp; cvta.to.shared.u64 tmp, %1; cvt.u32.u64 %0, tmp; }" : "=r"(a) : "l"(p));
    return a;
}
#define LDSM_X4(r0, r1, r2, r3, addr) \
    asm volatile("ldmatrix.sync.aligned.m8n8.x4.shared.b16 {%0,%1,%2,%3}, [%4];" \
                 : "=r"(r0), "=r"(r1), "=r"(r2), "=r"(r3) : "r"(addr))

#define MMAF16(d, a, b0, b1) \
    asm volatile("mma.sync.aligned.m16n8k16.row.col.f32.f16.f16.f32 " \
                 "{%0,%1,%2,%3}, {%4,%5,%6,%7}, {%8,%9}, {%0,%1,%2,%3};" \
                 : "+f"((d)[0]), "+f"((d)[1]), "+f"((d)[2]), "+f"((d)[3]) \
                 : "r"((a)[0]), "r"((a)[1]), "r"((a)[2]), "r"((a)[3]), "r"(b0), "r"(b1))

__device__ __forceinline__ uint32_t pack_h2(float a, float b) {
    __half2 v = __halves2half2(__float2half_rn(a), __float2half_rn(b));
    return *(uint32_t*)&v;
}
__device__ __forceinline__ void split_pair_h(float a, float b, uint32_t& hi, uint32_t& lo) {
    __half ha = __float2half_rn(a), hb = __float2half_rn(b);
    __half2 H = __halves2half2(ha, hb);
    __half2 L = __halves2half2(__float2half_rn(a - __half2float(ha)),
                               __float2half_rn(b - __half2float(hb)));
    hi = *(uint32_t*)&H;
    lo = *(uint32_t*)&L;
}

// ---------------- merged prep kernel ----------------
// blocks [0,2048): emb A-frag | [2048,2211): weights+c1+gate | 2211: score vectors
__global__ __launch_bounds__(256) void prep_kernel(
    const float* __restrict__ emb,
    const float* __restrict__ Wa, const float* __restrict__ W1,
    const float* __restrict__ W2, const float* __restrict__ b_align,
    const float* __restrict__ a_src1, const float* __restrict__ a_dst1,
    const float* __restrict__ gl, float* __restrict__ gate_out)
{
    int bid = blockIdx.x, t = threadIdx.x;
    if (bid < 2048) {
        int gid = bid * 256 + t;                 // 524288 emb A-frag words
        int lane = gid & 31;
        int ks = (gid >> 5) & 1;
        int grp = gid >> 6;
        int gr = lane >> 2, gc = (lane & 3) * 2;
        const float* base = emb + (size_t)grp * 16 * 32 + ks * 16;
        float v0 = base[gr * 32 + gc],           v1 = base[gr * 32 + gc + 1];
        float v2 = base[(gr + 8) * 32 + gc],     v3 = base[(gr + 8) * 32 + gc + 1];
        float v4 = base[gr * 32 + gc + 8],       v5 = base[gr * 32 + gc + 9];
        float v6 = base[(gr + 8) * 32 + gc + 8], v7 = base[(gr + 8) * 32 + gc + 9];
        uint4 H, L;
        split_pair_h(v0, v1, H.x, L.x);
        split_pair_h(v2, v3, H.y, L.y);
        split_pair_h(v4, v5, H.z, L.z);
        split_pair_h(v6, v7, H.w, L.w);
        g_embA_h[gid] = H;
        g_embA_l[gid] = L;
    } else if (bid < 2211) {
        int gid = (bid - 2048) * 256 + t;
        if (gid < 8192) {
            int reg = gid & 1, lane = (gid >> 1) & 31, gnt = (gid >> 6) & 63, ks = gid >> 12;
            int n = gnt * 8 + (lane >> 2);
            int k = ks * 16 + reg * 8 + (lane & 3) * 2;
            float v0 = 0.f, v1 = 0.f;
#pragma unroll 8
            for (int m = 0; m < 128; m++) {
                v0 = fmaf(Wa[k * 128 + m], W1[m * 512 + n], v0);
                v1 = fmaf(Wa[(k + 1) * 128 + m], W1[m * 512 + n], v1);
            }
            ((uint32_t*)g_w1pk)[gid] = pack_h2(v0, v1);
        } else if (gid < 40960) {
            int wid = gid - 8192;
            int reg = wid & 1, lane = (wid >> 1) & 31, gnt = (wid >> 6) & 15, ks = wid >> 10;
            int n = gnt * 8 + (lane >> 2);
            int k = ks * 16 + reg * 8 + (lane & 3) * 2;
            ((uint32_t*)g_w2pk)[wid] = pack_h2(W2[k * 128 + n], W2[(k + 1) * 128 + n]);
        } else if (gid < 41472) {
            int n = gid - 40960;
            float acc = 0.f;
#pragma unroll 8
            for (int m = 0; m < 128; m++) acc = fmaf(b_align[m], W1[m * 512 + n], acc);
            g_c1[n] = acc;
        } else if (gid < 41536) {
            int f = gid - 41472;
            if (gate_out != nullptr) gate_out[f] = 1.0f / (1.0f + expf(-gl[f]));
        }
    } else {
        // score vectors: w1a[sel*4+h] = Wa @ (W1_headslice @ a), c1a = b_align·t1
        __shared__ float t1[8][128];
        for (int i = 0; i < 4; i++) {
            int e = t * 4 + i;                   // 1024 entries
            int hs = e >> 7, m = e & 127;
            int h = hs & 3, sel = hs >> 2;
            const float* av = (sel ? a_dst1 : a_src1) + h * 128;
            float acc = 0.f;
#pragma unroll 8
            for (int nl = 0; nl < 128; nl++)
                acc = fmaf(W1[m * 512 + h * 128 + nl], av[nl], acc);
            t1[hs][m] = acc;
        }
        __syncthreads();
        {
            int hs = t >> 5, k = t & 31;
            float acc = 0.f;
#pragma unroll 8
            for (int m = 0; m < 128; m++) acc = fmaf(Wa[k * 128 + m], t1[hs][m], acc);
            g_w1a[t] = acc;
        }
        if (t < 8) {
            float acc = 0.f;
#pragma unroll 8
            for (int m = 0; m < 128; m++) acc = fmaf(b_align[m], t1[t][m], acc);
            g_c1a[t] = acc;
        }
    }
}

// ---------------- mega kernel ----------------
// dyn smem: [0,33792) h1/h2 fp32 64x132 | [33792,51200) o1 fp16 64x136
#define MG_O1  33792
#define MG_DYN 51200

__global__ __launch_bounds__(256, 3) void mega_kernel(
    const int* __restrict__ eidx, const float* __restrict__ gl,
    const float* __restrict__ emb,
    const float* __restrict__ b1,
    const float* __restrict__ a_src2, const float* __restrict__ a_dst2,
    const float* __restrict__ b2,
    const float* __restrict__ Wc1, const float* __restrict__ bc1,
    const float* __restrict__ Wc2, const float* __restrict__ bc2,
    float* __restrict__ outp)
{
    extern __shared__ __align__(16) char smem[];
    float* s_h1 = (float*)smem;                          // stride 132 fp32
    __half* s_o1 = (__half*)(smem + MG_O1);              // stride 136 fp16
    uint32_t sbO1 = smem_to_u32(smem) + MG_O1;

    __shared__ int   s_ed[192], s_esrc[192], s_osrc[192], s_startc[65], s_deg[64], s_cur[64];
    __shared__ float s_sc[2][4][64];                     // [sel][head][row]
    __shared__ float s_aprob[4 * 192];
    __shared__ float s_s2[2][64], s_smax2[1];            // GAT2 scores
    __shared__ float s_gv[8 * 128], s_hc[64];

    int b = blockIdx.x, t = threadIdx.x, lane = t & 31, w = t >> 5;
    int wm = w >> 1, wn = w & 1;
    int gr = lane >> 2, gc = (lane & 3) * 2;
    int node0 = b * 64;
    int r0 = wm * 16 + gr;

    // ---------- phase 0: edges + scores (all heads) ----------
    if (t < 64) { s_deg[t] = 0; s_cur[t] = 0; }
    if (t < 192) {
        int src, tt;
        if (t < 128) { src = eidx[b * 128 + t] - node0; tt = eidx[E_EDGES + b * 128 + t] - node0; }
        else         { src = t - 128; tt = src; }
        s_ed[t] = src | (tt << 8);
    }
    // per-(row, sel, head-pair) scores: score = gate_row * (emb_row · w1a + c1a)
    {
        int row = t & 63, sel = (t >> 6) & 1, hp = t >> 7;
        const float4* erow = (const float4*)(emb + (size_t)(node0 + row) * 32);
        float4 e0 = __ldg(erow), e1 = __ldg(erow + 1), e2 = __ldg(erow + 2), e3 = __ldg(erow + 3);
        float4 e4 = __ldg(erow + 4), e5 = __ldg(erow + 5), e6 = __ldg(erow + 6), e7 = __ldg(erow + 7);
        float gate = 1.0f / (1.0f + __expf(-__ldg(&gl[row])));
#pragma unroll
        for (int hh = 0; hh < 2; hh++) {
            int h = hp * 2 + hh, hs = sel * 4 + h;
            const float4* wv = (const float4*)(g_w1a + hs * 32);
            float s = __ldg(&g_c1a[hs]);
            float4 w0 = __ldg(wv), w1v = __ldg(wv + 1), w2v = __ldg(wv + 2), w3v = __ldg(wv + 3);
            float4 w4 = __ldg(wv + 4), w5 = __ldg(wv + 5), w6 = __ldg(wv + 6), w7 = __ldg(wv + 7);
            s += e0.x*w0.x + e0.y*w0.y + e0.z*w0.z + e0.w*w0.w;
            s += e1.x*w1v.x + e1.y*w1v.y + e1.z*w1v.z + e1.w*w1v.w;
            s += e2.x*w2v.x + e2.y*w2v.y + e2.z*w2v.z + e2.w*w2v.w;
            s += e3.x*w3v.x + e3.y*w3v.y + e3.z*w3v.z + e3.w*w3v.w;
            s += e4.x*w4.x + e4.y*w4.y + e4.z*w4.z + e4.w*w4.w;
            s += e5.x*w5.x + e5.y*w5.y + e5.z*w5.z + e5.w*w5.w;
            s += e6.x*w6.x + e6.y*w6.y + e6.z*w6.z + e6.w*w6.w;
            s += e7.x*w7.x + e7.y*w7.y + e7.z*w7.z + e7.w*w7.w;
            s_sc[sel][h][row] = gate * s;
        }
    }
    float gate0 = 1.0f / (1.0f + __expf(-__ldg(&gl[r0])));
    float gate1 = 1.0f / (1.0f + __expf(-__ldg(&gl[r0 + 8])));
    __syncthreads();
    if (t < 192) atomicAdd(&s_deg[s_ed[t] >> 8], 1);
    __syncthreads();
    if (w == 0) {                                        // warp-scan prefix over degrees
        int v0 = s_deg[lane * 2], v1 = s_deg[lane * 2 + 1];
        int p = v0 + v1, run = p;
#pragma unroll
        for (int off = 1; off < 32; off <<= 1) {
            int n = __shfl_up_sync(0xffffffffu, run, off);
            if (lane >= off) run += n;
        }
        s_startc[lane * 2] = run - p;
        s_startc[lane * 2 + 1] = run - p + v0;
        if (lane == 31) s_startc[64] = run;
    }
    __syncthreads();
    if (t < 192) {
        int tt = s_ed[t] >> 8, src = s_ed[t] & 255;
        int pos = atomicAdd(&s_cur[tt], 1);
        int slot = s_startc[tt] + pos;
        s_esrc[slot] = src;
        s_osrc[slot] = src * 132;
    }
    __syncthreads();

    // ---------- softmax for all 4 heads (serial per target) ----------
    {
        int h = t >> 6, tt = t & 63;
        int k0 = s_startc[tt], k1 = s_startc[tt + 1];
        float sd = s_sc[1][h][tt];
        float* ap = s_aprob + h * 192;
        float mx = -1e30f;
        for (int k = k0; k < k1; k++) {
            float sc = s_sc[0][h][s_esrc[k]] + sd;
            sc = sc > 0.f ? sc : 0.2f * sc;
            ap[k] = sc;
            mx = fmaxf(mx, sc);
        }
        float sum = 0.f;
        for (int k = k0; k < k1; k++) {
            float p = __expf(ap[k] - mx);
            ap[k] = p;
            sum += p;
        }
        float inv = 1.f / (sum + 1e-16f);
        for (int k = k0; k < k1; k++) ap[k] *= inv;
    }
    __syncthreads();

    float acc2[8][4] = {};                               // persistent GEMM2 accumulator

    // ---------- head loop: [MMA1+epi] SB [agg] SC [GEMM2] ----------
    for (int h = 0; h < HEADS; h++) {
        int hoff = h * 128;
        int grp = b * 4 + wm;

        float acc1[8][4] = {};
#pragma unroll
        for (int ks = 0; ks < 2; ks++) {
            uint4 H4 = __ldg(&g_embA_h[(size_t)(grp * 2 + ks) * 32 + lane]);
            uint4 L4 = __ldg(&g_embA_l[(size_t)(grp * 2 + ks) * 32 + lane]);
            uint32_t Ah[4] = { H4.x, H4.y, H4.z, H4.w };
            uint32_t Al[4] = { L4.x, L4.y, L4.z, L4.w };
            int base = (ks * 64 + h * 16 + wn * 8) * 32 + lane;
#pragma unroll
            for (int i = 0; i < 8; i++) {
                uint2 bw = __ldg(&g_w1pk[base + i * 32]);
                MMAF16(acc1[i], Ah, bw.x, bw.y);
                MMAF16(acc1[i], Al, bw.x, bw.y);
            }
        }
        // epilogue straight to h1 (safe: SC of prev head passed)
#pragma unroll
        for (int i = 0; i < 8; i++) {
            int col = wn * 64 + i * 8 + gc;
            float c0 = __ldg(&g_c1[hoff + col]), c1v = __ldg(&g_c1[hoff + col + 1]);
            s_h1[r0 * 132 + col]           = gate0 * (acc1[i][0] + c0);
            s_h1[r0 * 132 + col + 1]       = gate0 * (acc1[i][1] + c1v);
            s_h1[(r0 + 8) * 132 + col]     = gate1 * (acc1[i][2] + c0);
            s_h1[(r0 + 8) * 132 + col + 1] = gate1 * (acc1[i][3] + c1v);
        }
        __syncthreads();                                 // SB: h1 visible

        // aggregation (float4) + bias + elu -> o1 fp16
        {
            int tg = t >> 5, d = (t & 31) * 4;
            float4 bv = *(const float4*)(b1 + hoff + d);
            const float* ap = s_aprob + h * 192;
            for (int tt = tg * 8; tt < tg * 8 + 8; tt++) {
                float ax = 0.f, ay = 0.f, az = 0.f, aw = 0.f;
                int k0 = s_startc[tt], k1 = s_startc[tt + 1];
                for (int k = k0; k < k1; k++) {
                    float p = ap[k];
                    float4 v = *(const float4*)(s_h1 + s_osrc[k] + d);
                    ax = fmaf(p, v.x, ax);
                    ay = fmaf(p, v.y, ay);
                    az = fmaf(p, v.z, az);
                    aw = fmaf(p, v.w, aw);
                }
                float vx = ax + bv.x, vy = ay + bv.y, vz = az + bv.z, vw = aw + bv.w;
                vx = vx > 0.f ? vx : (__expf(vx) - 1.f);
                vy = vy > 0.f ? vy : (__expf(vy) - 1.f);
                vz = vz > 0.f ? vz : (__expf(vz) - 1.f);
                vw = vw > 0.f ? vw : (__expf(vw) - 1.f);
                uint2 pk;
                pk.x = pack_h2(vx, vy);
                pk.y = pack_h2(vz, vw);
                *(uint2*)(s_o1 + tt * 136 + d) = pk;
            }
        }
        __syncthreads();                                 // SC: o1 visible

        // GEMM2 partial (1-pass)
        {
            uint32_t aoff = (uint32_t)((wm * 16 + (lane & 15)) * 272 + (lane >> 4) * 16);
#pragma unroll
            for (int kk = 0; kk < 8; kk++) {
                uint32_t Ah[4];
                LDSM_X4(Ah[0], Ah[1], Ah[2], Ah[3], sbO1 + aoff + kk * 32);
                int base = ((h * 8 + kk) * 16 + wn * 8) * 32 + lane;
#pragma unroll
                for (int i = 0; i < 8; i++) {
                    uint2 bw = __ldg(&g_w2pk[base + i * 32]);
                    MMAF16(acc2[i], Ah, bw.x, bw.y);
                }
            }
        }
    }

    // ---------- h2 write (h1 region; safe: last SC passed, GEMM2 reads o1 only) ----------
#pragma unroll
    for (int i = 0; i < 8; i++) {
        int col = wn * 64 + i * 8 + gc;
        s_h1[r0 * 132 + col]           = acc2[i][0];
        s_h1[r0 * 132 + col + 1]       = acc2[i][1];
        s_h1[(r0 + 8) * 132 + col]     = acc2[i][2];
        s_h1[(r0 + 8) * 132 + col + 1] = acc2[i][3];
    }
    __syncthreads();

    // ---------- GAT2 scores (shfl over h2) ----------
    {
        float a0 = __ldg(&a_src2[lane * 4]);
        float a1 = __ldg(&a_src2[lane * 4 + 1]);
        float a2 = __ldg(&a_src2[lane * 4 + 2]);
        float a3 = __ldg(&a_src2[lane * 4 + 3]);
        float d0 = __ldg(&a_dst2[lane * 4]);
        float d1 = __ldg(&a_dst2[lane * 4 + 1]);
        float d2 = __ldg(&a_dst2[lane * 4 + 2]);
        float d3 = __ldg(&a_dst2[lane * 4 + 3]);
#pragma unroll
        for (int j = 0; j < 8; j++) {
            int i = w * 8 + j;
            float4 hv = *(const float4*)(s_h1 + i * 132 + lane * 4);
            float s1 = hv.x * a0 + hv.y * a1 + hv.z * a2 + hv.w * a3;
            float s2 = hv.x * d0 + hv.y * d1 + hv.z * d2 + hv.w * d3;
#pragma unroll
            for (int off = 16; off > 0; off >>= 1) {
                s1 += __shfl_xor_sync(0xffffffffu, s1, off);
                s2 += __shfl_xor_sync(0xffffffffu, s2, off);
            }
            if (lane == 0) { s_s2[0][i] = s1; s_s2[1][i] = s2; }
        }
    }
    __syncthreads();

    // ---------- GAT2 softmax (serial per target, t<64) ----------
    if (t < 64) {
        int tt = t;
        int k0 = s_startc[tt], k1 = s_startc[tt + 1];
        float sd = s_s2[1][tt];
        float mx = -1e30f;
        for (int k = k0; k < k1; k++) {
            float sc = s_s2[0][s_esrc[k]] + sd;
            sc = sc > 0.f ? sc : 0.2f * sc;
            s_aprob[k] = sc;
            mx = fmaxf(mx, sc);
        }
        float sum = 0.f;
        for (int k = k0; k < k1; k++) {
            float p = __expf(s_aprob[k] - mx);
            s_aprob[k] = p;
            sum += p;
        }
        float inv = 1.f / (sum + 1e-16f);
        for (int k = k0; k < k1; k++) s_aprob[k] *= inv;
    }
    __syncthreads();

    // ---------- GAT2 aggregation fused with mean pool (float4) ----------
    {
        int tg = t >> 5, d = (t & 31) * 4;
        float px = 0.f, py = 0.f, pz = 0.f, pw = 0.f;
        for (int tt = tg * 8; tt < tg * 8 + 8; tt++) {
            int k0 = s_startc[tt], k1 = s_startc[tt + 1];
            float ax = 0.f, ay = 0.f, az = 0.f, aw = 0.f;
            for (int k = k0; k < k1; k++) {
                float p = s_aprob[k];
                float4 v = *(const float4*)(s_h1 + s_osrc[k] + d);
                ax = fmaf(p, v.x, ax);
                ay = fmaf(p, v.y, ay);
                az = fmaf(p, v.z, az);
                aw = fmaf(p, v.w, aw);
            }
            px += ax; py += ay; pz += az; pw += aw;
        }
        s_gv[tg * 128 + d]     = px;
        s_gv[tg * 128 + d + 1] = py;
        s_gv[tg * 128 + d + 2] = pz;
        s_gv[tg * 128 + d + 3] = pw;
    }
    __syncthreads();

    // ---------- classifier ----------
    if (t < 128) {
        float g = 0.f;
#pragma unroll
        for (int q = 0; q < 8; q++) g += s_gv[q * 128 + t];
        s_gv[t] = g * (1.0f / 64.0f) + __ldg(&b2[t]);
    }
    __syncthreads();
    if (t < 64) {
        float a = __ldg(&bc1[t]);
#pragma unroll 8
        for (int d = 0; d < 128; d++) a = fmaf(s_gv[d], __ldg(&Wc1[d * 64 + t]), a);
        s_hc[t] = a > 0.f ? a : 0.01f * a;
    }
    __syncthreads();
    if (t < 16) {
        float a = __ldg(&bc2[t]);
#pragma unroll 8
        for (int j = 0; j < 64; j++) a = fmaf(s_hc[j], __ldg(&Wc2[j * 16 + t]), a);
        outp[(size_t)b * 16 + t] = a;
    }
}

// ---------------- launch ----------------
extern "C" void kernel_launch(void* const* d_in, const int* in_sizes, int n_in,
                              void* d_out, int out_size)
{
    const float* emb         = (const float*)d_in[0];
    const int*   edge_index  = (const int*)d_in[1];
    const float* W_align     = (const float*)d_in[3];
    const float* b_align     = (const float*)d_in[4];
    const float* gate_logits = (const float*)d_in[5];
    const float* W1          = (const float*)d_in[6];
    const float* a_src1      = (const float*)d_in[7];
    const float* a_dst1      = (const float*)d_in[8];
    const float* b1          = (const float*)d_in[9];
    const float* W2          = (const float*)d_in[10];
    const float* a_src2      = (const float*)d_in[11];
    const float* a_dst2      = (const float*)d_in[12];
    const float* b2          = (const float*)d_in[13];
    const float* Wc1         = (const float*)d_in[14];
    const float* bc1         = (const float*)d_in[15];
    const float* Wc2         = (const float*)d_in[16];
    const float* bc2         = (const float*)d_in[17];
    float* out = (float*)d_out;

    cudaFuncSetAttribute(mega_kernel, cudaFuncAttributeMaxDynamicSharedMemorySize, MG_DYN);

    float* gate_out = (out_size >= 64) ? (out + (out_size - 64)) : nullptr;

    // 1) merged prep: emb A-frags + weight fragments + score vectors + gate
    prep_kernel<<<2212, 256>>>(emb, W_align, W1, W2, b_align,
                               a_src1, a_dst1, gate_logits, gate_out);

    // 2) fused per-graph pipeline
    mega_kernel<<<B_GRAPHS, 256, MG_DYN>>>(
        edge_index, gate_logits, emb,
        b1, a_src2, a_dst2, b2,
        Wc1, bc1, Wc2, bc2, out);
}

// round 11
// speedup vs baseline: 3.9761x; 1.0669x over previous
#include <cuda_runtime.h>
#include <cuda_fp16.h>
#include <math.h>
#include <cstdint>

// ---------------- problem constants ----------------
#define B_GRAPHS 2048
#define F_NODES  64
#define D_IN     32
#define HDIM     128
#define HEADS    4
#define NC       16
#define EPG      128
#define N_NODES  (B_GRAPHS * F_NODES)        // 131072
#define E_EDGES  (B_GRAPHS * EPG)            // 262144

// ---------------- device-global scratch ----------------
__device__ uint2 g_w1pk[2 * 64 * 32];         // W1'=Wa@W1 B-frag fp16
__device__ float g_c1[512];                   // b_align @ W1
__device__ uint2 g_w2pk[32 * 16 * 32];        // W2^T B-frag fp16
__device__ uint4 g_embA_h[(size_t)8192 * 2 * 32];  // emb A-frag hi
__device__ uint4 g_embA_l[(size_t)8192 * 2 * 32];  // emb A-frag lo
__device__ float g_w1a[8 * 32];               // [sel*4+h][32] = Wa@(W1@a)
__device__ float g_c1a[8];                    // c1 · a

// ---------------- PTX helpers (sm_80+; no tcgen05 — ptxas targets compute_103) ----------------
__device__ __forceinline__ uint32_t smem_to_u32(const void* p) {
    uint32_t a;
    asm("{ .reg .u64 tmp; cvta.to.shared.u64 tmp, %1; cvt.u32.u64 %0, tmp; }" : "=r"(a) : "l"(p));
    return a;
}
#define LDSM_X4(r0, r1, r2, r3, addr) \
    asm volatile("ldmatrix.sync.aligned.m8n8.x4.shared.b16 {%0,%1,%2,%3}, [%4];" \
                 : "=r"(r0), "=r"(r1), "=r"(r2), "=r"(r3) : "r"(addr))
#define LDSM_X4T(r0, r1, r2, r3, addr) \
    asm volatile("ldmatrix.sync.aligned.m8n8.x4.trans.shared.b16 {%0,%1,%2,%3}, [%4];" \
                 : "=r"(r0), "=r"(r1), "=r"(r2), "=r"(r3) : "r"(addr))

#define MMAF16(d, a, b0, b1) \
    asm volatile("mma.sync.aligned.m16n8k16.row.col.f32.f16.f16.f32 " \
                 "{%0,%1,%2,%3}, {%4,%5,%6,%7}, {%8,%9}, {%0,%1,%2,%3};" \
                 : "+f"((d)[0]), "+f"((d)[1]), "+f"((d)[2]), "+f"((d)[3]) \
                 : "r"((a)[0]), "r"((a)[1]), "r"((a)[2]), "r"((a)[3]), "r"(b0), "r"(b1))

__device__ __forceinline__ uint32_t pack_h2(float a, float b) {
    __half2 v = __halves2half2(__float2half_rn(a), __float2half_rn(b));
    return *(uint32_t*)&v;
}
__device__ __forceinline__ void split_pair_h(float a, float b, uint32_t& hi, uint32_t& lo) {
    __half ha = __float2half_rn(a), hb = __float2half_rn(b);
    __half2 H = __halves2half2(ha, hb);
    __half2 L = __halves2half2(__float2half_rn(a - __half2float(ha)),
                               __float2half_rn(b - __half2float(hb)));
    hi = *(uint32_t*)&H;
    lo = *(uint32_t*)&L;
}

// ---------------- merged prep kernel (unchanged from R10) ----------------
__global__ __launch_bounds__(256) void prep_kernel(
    const float* __restrict__ emb,
    const float* __restrict__ Wa, const float* __restrict__ W1,
    const float* __restrict__ W2, const float* __restrict__ b_align,
    const float* __restrict__ a_src1, const float* __restrict__ a_dst1,
    const float* __restrict__ gl, float* __restrict__ gate_out)
{
    int bid = blockIdx.x, t = threadIdx.x;
    if (bid < 2048) {
        int gid = bid * 256 + t;
        int lane = gid & 31;
        int ks = (gid >> 5) & 1;
        int grp = gid >> 6;
        int gr = lane >> 2, gc = (lane & 3) * 2;
        const float* base = emb + (size_t)grp * 16 * 32 + ks * 16;
        float v0 = base[gr * 32 + gc],           v1 = base[gr * 32 + gc + 1];
        float v2 = base[(gr + 8) * 32 + gc],     v3 = base[(gr + 8) * 32 + gc + 1];
        float v4 = base[gr * 32 + gc + 8],       v5 = base[gr * 32 + gc + 9];
        float v6 = base[(gr + 8) * 32 + gc + 8], v7 = base[(gr + 8) * 32 + gc + 9];
        uint4 H, L;
        split_pair_h(v0, v1, H.x, L.x);
        split_pair_h(v2, v3, H.y, L.y);
        split_pair_h(v4, v5, H.z, L.z);
        split_pair_h(v6, v7, H.w, L.w);
        g_embA_h[gid] = H;
        g_embA_l[gid] = L;
    } else if (bid < 2211) {
        int gid = (bid - 2048) * 256 + t;
        if (gid < 8192) {
            int reg = gid & 1, lane = (gid >> 1) & 31, gnt = (gid >> 6) & 63, ks = gid >> 12;
            int n = gnt * 8 + (lane >> 2);
            int k = ks * 16 + reg * 8 + (lane & 3) * 2;
            float v0 = 0.f, v1 = 0.f;
#pragma unroll 8
            for (int m = 0; m < 128; m++) {
                v0 = fmaf(Wa[k * 128 + m], W1[m * 512 + n], v0);
                v1 = fmaf(Wa[(k + 1) * 128 + m], W1[m * 512 + n], v1);
            }
            ((uint32_t*)g_w1pk)[gid] = pack_h2(v0, v1);
        } else if (gid < 40960) {
            int wid = gid - 8192;
            int reg = wid & 1, lane = (wid >> 1) & 31, gnt = (wid >> 6) & 15, ks = wid >> 10;
            int n = gnt * 8 + (lane >> 2);
            int k = ks * 16 + reg * 8 + (lane & 3) * 2;
            ((uint32_t*)g_w2pk)[wid] = pack_h2(W2[k * 128 + n], W2[(k + 1) * 128 + n]);
        } else if (gid < 41472) {
            int n = gid - 40960;
            float acc = 0.f;
#pragma unroll 8
            for (int m = 0; m < 128; m++) acc = fmaf(b_align[m], W1[m * 512 + n], acc);
            g_c1[n] = acc;
        } else if (gid < 41536) {
            int f = gid - 41472;
            if (gate_out != nullptr) gate_out[f] = 1.0f / (1.0f + expf(-gl[f]));
        }
    } else {
        __shared__ float t1[8][128];
        for (int i = 0; i < 4; i++) {
            int e = t * 4 + i;
            int hs = e >> 7, m = e & 127;
            int h = hs & 3, sel = hs >> 2;
            const float* av = (sel ? a_dst1 : a_src1) + h * 128;
            float acc = 0.f;
#pragma unroll 8
            for (int nl = 0; nl < 128; nl++)
                acc = fmaf(W1[m * 512 + h * 128 + nl], av[nl], acc);
            t1[hs][m] = acc;
        }
        __syncthreads();
        {
            int hs = t >> 5, k = t & 31;
            float acc = 0.f;
#pragma unroll 8
            for (int m = 0; m < 128; m++) acc = fmaf(Wa[k * 128 + m], t1[hs][m], acc);
            g_w1a[t] = acc;
        }
        if (t < 8) {
            float acc = 0.f;
#pragma unroll 8
            for (int m = 0; m < 128; m++) acc = fmaf(b_align[m], t1[t][m], acc);
            g_c1a[t] = acc;
        }
    }
}

// ---------------- mega kernel ----------------
// dyn smem (51200 B total, occ 3):
//  X region [0,33792): during head loop = h1 fp16 [64][136] @0 (17408) + alpha fp16 [64][72] @17408 (9216)
//                      after head loop  = h2 fp32 [64][132] @0 (33792)
//  o1 fp16 [64][136] @33792 (17408)
#define MG_ALPHA 17408
#define MG_O1    33792
#define MG_DYN   51200

__global__ __launch_bounds__(256, 3) void mega_kernel(
    const int* __restrict__ eidx, const float* __restrict__ gl,
    const float* __restrict__ emb,
    const float* __restrict__ b1,
    const float* __restrict__ a_src2, const float* __restrict__ a_dst2,
    const float* __restrict__ b2,
    const float* __restrict__ Wc1, const float* __restrict__ bc1,
    const float* __restrict__ Wc2, const float* __restrict__ bc2,
    float* __restrict__ outp)
{
    extern __shared__ __align__(16) char smem[];
    __half* s_h1  = (__half*)smem;                       // stride 136 halves
    __half* s_al  = (__half*)(smem + MG_ALPHA);          // stride 72 halves
    float*  s_h2  = (float*)smem;                        // stride 132 (post-loop)
    __half* s_o1  = (__half*)(smem + MG_O1);             // stride 136 halves
    uint32_t sb    = smem_to_u32(smem);
    uint32_t sbAl  = sb + MG_ALPHA;
    uint32_t sbO1  = sb + MG_O1;

    __shared__ int   s_ed[192], s_esrc[192], s_startc[65], s_deg[64], s_cur[64];
    __shared__ float s_sc[2][4][64];                     // GAT1 [sel][head][row]
    __shared__ float s_aprob[4 * 192];
    __shared__ float s_s2[128];                          // GAT2 scores: [0,64) src, [64,128) dst
    __shared__ float s_q[64], s_g[128], s_hc[64];

    int b = blockIdx.x, t = threadIdx.x, lane = t & 31, w = t >> 5;
    int wm = w >> 1, wn = w & 1;
    int gr = lane >> 2, gc = (lane & 3) * 2;
    int node0 = b * 64;
    int r0 = wm * 16 + gr;

    // ---------- phase 0 ----------
    if (t < 64) { s_deg[t] = 0; s_cur[t] = 0; s_q[t] = 0.f; }
    if (t >= 64 && t < 192) ((float*)s_s2)[t - 64] = 0.f;
    if (t < 192) {
        int src, tt;
        if (t < 128) { src = eidx[b * 128 + t] - node0; tt = eidx[E_EDGES + b * 128 + t] - node0; }
        else         { src = t - 128; tt = src; }
        s_ed[t] = src | (tt << 8);
    }
    // zero alpha region (2304 words)
    {
        uint32_t* az = (uint32_t*)(smem + MG_ALPHA);
#pragma unroll
        for (int i = 0; i < 9; i++) az[t + i * 256] = 0u;
    }
    // per-(row, sel, head-pair) GAT1 scores: gate_row * (emb_row · w1a + c1a)
    {
        int row = t & 63, sel = (t >> 6) & 1, hp = t >> 7;
        const float4* erow = (const float4*)(emb + (size_t)(node0 + row) * 32);
        float4 e0 = __ldg(erow), e1 = __ldg(erow + 1), e2 = __ldg(erow + 2), e3 = __ldg(erow + 3);
        float4 e4 = __ldg(erow + 4), e5 = __ldg(erow + 5), e6 = __ldg(erow + 6), e7 = __ldg(erow + 7);
        float gate = 1.0f / (1.0f + __expf(-__ldg(&gl[row])));
#pragma unroll
        for (int hh = 0; hh < 2; hh++) {
            int h = hp * 2 + hh, hs = sel * 4 + h;
            const float4* wv = (const float4*)(g_w1a + hs * 32);
            float s = __ldg(&g_c1a[hs]);
            float4 w0 = __ldg(wv), w1v = __ldg(wv + 1), w2v = __ldg(wv + 2), w3v = __ldg(wv + 3);
            float4 w4 = __ldg(wv + 4), w5 = __ldg(wv + 5), w6 = __ldg(wv + 6), w7 = __ldg(wv + 7);
            s += e0.x*w0.x + e0.y*w0.y + e0.z*w0.z + e0.w*w0.w;
            s += e1.x*w1v.x + e1.y*w1v.y + e1.z*w1v.z + e1.w*w1v.w;
            s += e2.x*w2v.x + e2.y*w2v.y + e2.z*w2v.z + e2.w*w2v.w;
            s += e3.x*w3v.x + e3.y*w3v.y + e3.z*w3v.z + e3.w*w3v.w;
            s += e4.x*w4.x + e4.y*w4.y + e4.z*w4.z + e4.w*w4.w;
            s += e5.x*w5.x + e5.y*w5.y + e5.z*w5.z + e5.w*w5.w;
            s += e6.x*w6.x + e6.y*w6.y + e6.z*w6.z + e6.w*w6.w;
            s += e7.x*w7.x + e7.y*w7.y + e7.z*w7.z + e7.w*w7.w;
            s_sc[sel][h][row] = gate * s;
        }
    }
    float gate0 = 1.0f / (1.0f + __expf(-__ldg(&gl[r0])));
    float gate1 = 1.0f / (1.0f + __expf(-__ldg(&gl[r0 + 8])));
    __syncthreads();
    if (t < 192) atomicAdd(&s_deg[s_ed[t] >> 8], 1);
    __syncthreads();
    if (w == 0) {
        int v0 = s_deg[lane * 2], v1 = s_deg[lane * 2 + 1];
        int p = v0 + v1, run = p;
#pragma unroll
        for (int off = 1; off < 32; off <<= 1) {
            int n = __shfl_up_sync(0xffffffffu, run, off);
            if (lane >= off) run += n;
        }
        s_startc[lane * 2] = run - p;
        s_startc[lane * 2 + 1] = run - p + v0;
        if (lane == 31) s_startc[64] = run;
    }
    __syncthreads();
    if (t < 192) {
        int tt = s_ed[t] >> 8, src = s_ed[t] & 255;
        int pos = atomicAdd(&s_cur[tt], 1);
        s_esrc[s_startc[tt] + pos] = src;
    }
    __syncthreads();

    // ---------- GAT1 softmax, all 4 heads (serial per target) ----------
    {
        int h = t >> 6, tt = t & 63;
        int k0 = s_startc[tt], k1 = s_startc[tt + 1];
        float sd = s_sc[1][h][tt];
        float* ap = s_aprob + h * 192;
        float mx = -1e30f;
        for (int k = k0; k < k1; k++) {
            float sc = s_sc[0][h][s_esrc[k]] + sd;
            sc = sc > 0.f ? sc : 0.2f * sc;
            ap[k] = sc;
            mx = fmaxf(mx, sc);
        }
        float sum = 0.f;
        for (int k = k0; k < k1; k++) {
            float p = __expf(ap[k] - mx);
            ap[k] = p;
            sum += p;
        }
        float inv = 1.f / (sum + 1e-16f);
        for (int k = k0; k < k1; k++) ap[k] *= inv;
    }
    __syncthreads();

    float acc2[8][4] = {};                               // persistent GEMM2 accumulator

    // ---------- head loop: [GEMM1 + h1 fp16 + alpha build] S1 [agg MMA -> o1] S2 [GEMM2] ----------
    for (int h = 0; h < HEADS; h++) {
        int hoff = h * 128;
        int grp = b * 4 + wm;

        float acc1[8][4] = {};
#pragma unroll
        for (int ks = 0; ks < 2; ks++) {
            uint4 H4 = __ldg(&g_embA_h[(size_t)(grp * 2 + ks) * 32 + lane]);
            uint4 L4 = __ldg(&g_embA_l[(size_t)(grp * 2 + ks) * 32 + lane]);
            uint32_t Ah[4] = { H4.x, H4.y, H4.z, H4.w };
            uint32_t Al[4] = { L4.x, L4.y, L4.z, L4.w };
            int base = (ks * 64 + h * 16 + wn * 8) * 32 + lane;
#pragma unroll
            for (int i = 0; i < 8; i++) {
                uint2 bw = __ldg(&g_w1pk[base + i * 32]);
                MMAF16(acc1[i], Ah, bw.x, bw.y);
                MMAF16(acc1[i], Al, bw.x, bw.y);
            }
        }
        // epilogue: h1 = gate*(acc + c1) -> fp16 smem
#pragma unroll
        for (int i = 0; i < 8; i++) {
            int col = wn * 64 + i * 8 + gc;
            float c0 = __ldg(&g_c1[hoff + col]), c1v = __ldg(&g_c1[hoff + col + 1]);
            *(uint32_t*)(s_h1 + r0 * 136 + col) =
                pack_h2(gate0 * (acc1[i][0] + c0), gate0 * (acc1[i][1] + c1v));
            *(uint32_t*)(s_h1 + (r0 + 8) * 136 + col) =
                pack_h2(gate1 * (acc1[i][2] + c0), gate1 * (acc1[i][3] + c1v));
        }
        // alpha build: thread-per-target, zero touched then accumulate (handles dup edges)
        if (t < 64) {
            int tt = t;
            int k0 = s_startc[tt], k1 = s_startc[tt + 1];
            const float* ap = s_aprob + h * 192;
            __half* row = s_al + tt * 72;
            for (int k = k0; k < k1; k++) row[s_esrc[k]] = __float2half_rn(0.f);
            for (int k = k0; k < k1; k++) {
                int s = s_esrc[k];
                row[s] = __float2half_rn(__half2float(row[s]) + ap[k]);
            }
        }
        __syncthreads();                                 // S1: h1 + alpha visible

        // agg MMA: o1 = alpha @ h1  (M=64 tgt, K=64 src, N=128 dims), n split in 2 halves
        {
            uint32_t aAddr = sbAl + (uint32_t)((wm * 16 + (lane & 15)) * 144 + (lane >> 4) * 16);
#pragma unroll
            for (int nh = 0; nh < 2; nh++) {
                int n0 = wn * 64 + nh * 32;
                uint32_t bAddr = sb + (uint32_t)((lane & 15) * 272 + (n0 + (lane >> 4) * 8) * 2);
                float ag[4][4] = {};
#pragma unroll
                for (int ks = 0; ks < 4; ks++) {
                    uint32_t A[4], B0[4], B1[4];
                    LDSM_X4(A[0], A[1], A[2], A[3], aAddr + ks * 32);
                    LDSM_X4T(B0[0], B0[1], B0[2], B0[3], bAddr + ks * 4352);
                    LDSM_X4T(B1[0], B1[1], B1[2], B1[3], bAddr + 32 + ks * 4352);
                    MMAF16(ag[0], A, B0[0], B0[1]);
                    MMAF16(ag[1], A, B0[2], B0[3]);
                    MMAF16(ag[2], A, B1[0], B1[1]);
                    MMAF16(ag[3], A, B1[2], B1[3]);
                }
                // epi: + b1, elu, fp16 -> o1
#pragma unroll
                for (int nt = 0; nt < 4; nt++) {
                    int col = n0 + nt * 8 + gc;
                    float b0v = __ldg(&b1[hoff + col]), b1v = __ldg(&b1[hoff + col + 1]);
                    float vx = ag[nt][0] + b0v, vy = ag[nt][1] + b1v;
                    float vz = ag[nt][2] + b0v, vw = ag[nt][3] + b1v;
                    vx = vx > 0.f ? vx : (__expf(vx) - 1.f);
                    vy = vy > 0.f ? vy : (__expf(vy) - 1.f);
                    vz = vz > 0.f ? vz : (__expf(vz) - 1.f);
                    vw = vw > 0.f ? vw : (__expf(vw) - 1.f);
                    *(uint32_t*)(s_o1 + r0 * 136 + col) = pack_h2(vx, vy);
                    *(uint32_t*)(s_o1 + (r0 + 8) * 136 + col) = pack_h2(vz, vw);
                }
            }
        }
        __syncthreads();                                 // S2: o1 visible

        // GEMM2 partial (1-pass): acc2 += o1_head @ W2[head]
        {
            uint32_t aoff = (uint32_t)((wm * 16 + (lane & 15)) * 272 + (lane >> 4) * 16);
#pragma unroll
            for (int kk = 0; kk < 8; kk++) {
                uint32_t Ah[4];
                LDSM_X4(Ah[0], Ah[1], Ah[2], Ah[3], sbO1 + aoff + kk * 32);
                int base = ((h * 8 + kk) * 16 + wn * 8) * 32 + lane;
#pragma unroll
                for (int i = 0; i < 8; i++) {
                    uint2 bw = __ldg(&g_w2pk[base + i * 32]);
                    MMAF16(acc2[i], Ah, bw.x, bw.y);
                }
            }
        }
    }

    // ---------- h2 write (fp32, X region) + GAT2 score partials from registers ----------
    {
        float p1s = 0.f, p1d = 0.f, p2s = 0.f, p2d = 0.f;
#pragma unroll
        for (int i = 0; i < 8; i++) {
            int col = wn * 64 + i * 8 + gc;
            s_h2[r0 * 132 + col]           = acc2[i][0];
            s_h2[r0 * 132 + col + 1]       = acc2[i][1];
            s_h2[(r0 + 8) * 132 + col]     = acc2[i][2];
            s_h2[(r0 + 8) * 132 + col + 1] = acc2[i][3];
            float as0 = __ldg(&a_src2[col]), as1 = __ldg(&a_src2[col + 1]);
            float ad0 = __ldg(&a_dst2[col]), ad1 = __ldg(&a_dst2[col + 1]);
            p1s += acc2[i][0] * as0 + acc2[i][1] * as1;
            p1d += acc2[i][0] * ad0 + acc2[i][1] * ad1;
            p2s += acc2[i][2] * as0 + acc2[i][3] * as1;
            p2d += acc2[i][2] * ad0 + acc2[i][3] * ad1;
        }
        atomicAdd(&s_s2[r0], p1s);
        atomicAdd(&s_s2[64 + r0], p1d);
        atomicAdd(&s_s2[r0 + 8], p2s);
        atomicAdd(&s_s2[64 + r0 + 8], p2d);
    }
    __syncthreads();

    // ---------- GAT2 softmax (serial per target) ----------
    if (t < 64) {
        int tt = t;
        int k0 = s_startc[tt], k1 = s_startc[tt + 1];
        float sd = s_s2[64 + tt];
        float mx = -1e30f;
        for (int k = k0; k < k1; k++) {
            float sc = s_s2[s_esrc[k]] + sd;
            sc = sc > 0.f ? sc : 0.2f * sc;
            s_aprob[k] = sc;
            mx = fmaxf(mx, sc);
        }
        float sum = 0.f;
        for (int k = k0; k < k1; k++) {
            float p = __expf(s_aprob[k] - mx);
            s_aprob[k] = p;
            sum += p;
        }
        float inv = 1.f / (sum + 1e-16f);
        for (int k = k0; k < k1; k++) s_aprob[k] *= inv;
    }
    __syncthreads();

    // ---------- pooled GAT2: q[src] = sum_t alpha2[t][src]; g = q·h2/64 + b2 ----------
    if (t < 192) atomicAdd(&s_q[s_esrc[t]], s_aprob[t]);
    __syncthreads();
    if (t < 128) {
        float a = 0.f;
#pragma unroll 8
        for (int src = 0; src < 64; src++)
            a = fmaf(s_q[src], s_h2[src * 132 + t], a);
        s_g[t] = a * (1.0f / 64.0f) + __ldg(&b2[t]);
    }
    __syncthreads();

    // ---------- classifier ----------
    if (t < 64) {
        float a = __ldg(&bc1[t]);
#pragma unroll 8
        for (int d = 0; d < 128; d++) a = fmaf(s_g[d], __ldg(&Wc1[d * 64 + t]), a);
        s_hc[t] = a > 0.f ? a : 0.01f * a;
    }
    __syncthreads();
    if (t < 16) {
        float a = __ldg(&bc2[t]);
#pragma unroll 8
        for (int j = 0; j < 64; j++) a = fmaf(s_hc[j], __ldg(&Wc2[j * 16 + t]), a);
        outp[(size_t)b * 16 + t] = a;
    }
}

// ---------------- launch ----------------
extern "C" void kernel_launch(void* const* d_in, const int* in_sizes, int n_in,
                              void* d_out, int out_size)
{
    const float* emb         = (const float*)d_in[0];
    const int*   edge_index  = (const int*)d_in[1];
    const float* W_align     = (const float*)d_in[3];
    const float* b_align     = (const float*)d_in[4];
    const float* gate_logits = (const float*)d_in[5];
    const float* W1          = (const float*)d_in[6];
    const float* a_src1      = (const float*)d_in[7];
    const float* a_dst1      = (const float*)d_in[8];
    const float* b1          = (const float*)d_in[9];
    const float* W2          = (const float*)d_in[10];
    const float* a_src2      = (const float*)d_in[11];
    const float* a_dst2      = (const float*)d_in[12];
    const float* b2          = (const float*)d_in[13];
    const float* Wc1         = (const float*)d_in[14];
    const float* bc1         = (const float*)d_in[15];
    const float* Wc2         = (const float*)d_in[16];
    const float* bc2         = (const float*)d_in[17];
    float* out = (float*)d_out;

    cudaFuncSetAttribute(mega_kernel, cudaFuncAttributeMaxDynamicSharedMemorySize, MG_DYN);

    float* gate_out = (out_size >= 64) ? (out + (out_size - 64)) : nullptr;

    // 1) merged prep: emb A-frags + weight fragments + score vectors + gate
    prep_kernel<<<2212, 256>>>(emb, W_align, W1, W2, b_align,
                               a_src1, a_dst1, gate_logits, gate_out);

    // 2) fused per-graph pipeline (tensor-core aggregation)
    mega_kernel<<<B_GRAPHS, 256, MG_DYN>>>(
        edge_index, gate_logits, emb,
        b1, a_src2, a_dst2, b2,
        Wc1, bc1, Wc2, bc2, out);
}